// round 10
// baseline (speedup 1.0000x reference)
#include <cuda_runtime.h>
#include <cuda_bf16.h>
#include <cstdint>

#define TLEN  512
#define BATCH 1024
#define HID   128
#define G4    512
#define NCLS  6
#define BT    16
#define KPAD0 144    // 16 (padded x, C=9) + 128 (h)
#define KPAD1 128    // h only (input projection precomputed)
#define SEGT  128    // timesteps per L1 segment
#define NSEG  (TLEN / SEGT)

// ---------------------------------------------------------------------------
// Scratch (device globals; total must stay well under 2 GB — host shadow .bss)
// ---------------------------------------------------------------------------
__device__ __align__(16) float g_xT[(size_t)TLEN * BATCH * 16];              // 32 MB
__device__ __align__(16) __nv_bfloat16 g_ah[(size_t)TLEN * BATCH * 256];     // 256 MB
__device__ __align__(16) __nv_bfloat16 g_al[(size_t)TLEN * BATCH * 256];     // 256 MB
__device__ __align__(16) float g_xg1f[(size_t)SEGT * BATCH * G4];            // 256 MB (fwd chunk)
__device__ __align__(16) float g_xg1r[(size_t)SEGT * BATCH * G4];            // 256 MB (rev chunk)
__device__ __align__(16) float g_hstate[2 * BATCH * HID];                    // 1 MB
__device__ __align__(16) float g_cstate[2 * BATCH * HID];                    // 1 MB
__device__ __align__(16) float g_final[(size_t)BATCH * 256];
__device__ __align__(16) float g_wp0[2 * KPAD0 * G4];
__device__ __align__(16) float g_wp1[2 * KPAD1 * G4];
__device__ __align__(16) __nv_bfloat16 g_wb1h[2 * 512 * 256];                // W_ih_l1 bf16 hi [dir][n][k]
__device__ __align__(16) __nv_bfloat16 g_wb1l[2 * 512 * 256];                // W_ih_l1 bf16 lo
__device__ float g_bias[4 * G4];

// Single dynamic-smem symbol (one type everywhere)
extern __shared__ char smem_raw[];

// ---------------------------------------------------------------------------
// Scalar helpers
// ---------------------------------------------------------------------------
__device__ __forceinline__ unsigned long long ffma2(unsigned long long a,
                                                    unsigned long long b,
                                                    unsigned long long c) {
    unsigned long long d;
    asm("fma.rn.f32x2 %0, %1, %2, %3;" : "=l"(d) : "l"(a), "l"(b), "l"(c));
    return d;
}
__device__ __forceinline__ float upsum(unsigned long long a) {
    float lo, hi;
    asm("mov.b64 {%0, %1}, %2;" : "=f"(lo), "=f"(hi) : "l"(a));
    return lo + hi;
}
__device__ __forceinline__ unsigned long long pack2(float lo, float hi) {
    unsigned long long r;
    asm("mov.b64 %0, {%1, %2};" : "=l"(r) : "f"(lo), "f"(hi));
    return r;
}
__device__ __forceinline__ float sigm(float x) {
    return __fdividef(1.f, 1.f + __expf(-x));
}
__device__ __forceinline__ float tanhx(float x) {
    return __fdividef(2.f, 1.f + __expf(-2.f * x)) - 1.f;
}

// mma.sync m16n8k16 bf16 -> fp32 accumulate (sm_80+, valid on family target)
__device__ __forceinline__ void mma16816(float* c,
                                         uint32_t a0, uint32_t a1, uint32_t a2, uint32_t a3,
                                         uint32_t b0, uint32_t b1) {
    asm volatile(
        "mma.sync.aligned.m16n8k16.row.col.f32.bf16.bf16.f32 "
        "{%0,%1,%2,%3}, {%4,%5,%6,%7}, {%8,%9}, {%0,%1,%2,%3};"
        : "+f"(c[0]), "+f"(c[1]), "+f"(c[2]), "+f"(c[3])
        : "r"(a0), "r"(a1), "r"(a2), "r"(a3), "r"(b0), "r"(b1));
}

// ---------------------------------------------------------------------------
// Prep: transpose x [B,9,T] -> g_xT [T,B,16] (cols 9..15 zero)
// ---------------------------------------------------------------------------
__global__ void k_transpose(const float* __restrict__ x) {
    size_t o = (size_t)blockIdx.x * blockDim.x + threadIdx.x;
    if (o >= (size_t)TLEN * BATCH * 16) return;
    int c = (int)(o & 15);
    size_t tb = o >> 4;
    int b = (int)(tb % BATCH);
    int t = (int)(tb / BATCH);
    g_xT[o] = (c < 9) ? x[((size_t)b * 9 + c) * TLEN + t] : 0.f;
}

// ---------------------------------------------------------------------------
// Pack scan weights, quad-interleaved wp[kk][g][4]; bias sums.
// which: 0=l0f 1=l0r (K=144), 2=l1f 3=l1r (K=128, h only)
// ---------------------------------------------------------------------------
struct WPtrs { const float* p[16]; };

__global__ void k_pack_whh(WPtrs W) {
    const int which = blockIdx.y;
    const float* wih = W.p[which * 4 + 0];
    const float* whh = W.p[which * 4 + 1];
    const float* bih = W.p[which * 4 + 2];
    const float* bhh = W.p[which * 4 + 3];
    const int kpad = (which < 2) ? KPAD0 : KPAD1;
    int o = blockIdx.x * blockDim.x + threadIdx.x;
    if (o < G4) g_bias[which * G4 + o] = bih[o] + bhh[o];
    if (o >= kpad * G4) return;
    int kk = o / (G4 * 4);
    int rem = o % (G4 * 4);
    int g = rem / 4, j = rem % 4;
    int k = kk * 4 + j;
    float v = 0.f;
    if (which < 2) {
        if (k < 9)                      v = wih[g * 9 + k];
        else if (k >= 16 && k < 144)    v = whh[g * HID + (k - 16)];
        g_wp0[which * KPAD0 * G4 + o] = v;
    } else {
        v = whh[g * HID + k];
        g_wp1[(which - 2) * KPAD1 * G4 + o] = v;
    }
}

// ---------------------------------------------------------------------------
// Pack W_ih_l1 fp32 -> bf16 hi/lo, plain [dir][512 n][256 k] row-major
// ---------------------------------------------------------------------------
__global__ void k_pack_wb1(const float* __restrict__ wf, const float* __restrict__ wr) {
    int o = blockIdx.x * blockDim.x + threadIdx.x;
    if (o >= 2 * G4 * 256) return;
    int dir = o / (G4 * 256);
    int rem = o % (G4 * 256);
    const float* w = dir ? wr : wf;
    float v = w[rem];
    __nv_bfloat16 h = __float2bfloat16(v);
    __nv_bfloat16 l = __float2bfloat16(v - __bfloat162float(h));
    g_wb1h[o] = h;
    g_wb1l[o] = l;
}

// ---------------------------------------------------------------------------
// xg1 chunk: for segment seg, per dir, compute xg = out0 @ W_ih_l1^T + bias
// over SEGT timesteps. Grid (512, 8): y = dir*4 + ntile. Block 256 thr =
// 8 warps (4m x 2n), tile 256m x 128n x K256, atom m16n8k16, bf16 3-split.
// ---------------------------------------------------------------------------
#define BSTR 264   // B smem row stride (bf16)
#define ASTR 40    // A smem row stride (bf16)

__global__ void __launch_bounds__(256, 1) k_xg1(int seg) {
    __nv_bfloat16* sBh = (__nv_bfloat16*)smem_raw;
    __nv_bfloat16* sBl = sBh + 128 * BSTR;
    __nv_bfloat16* sAh = sBl + 128 * BSTR;
    __nv_bfloat16* sAl = sAh + 256 * ASTR;

    const int tid  = threadIdx.x;
    const int wid  = tid >> 5, lane = tid & 31;
    const int g    = lane >> 2, tig = lane & 3;
    const int wm   = (wid & 3) * 64;
    const int wn   = (wid >> 2) * 64;
    const int dir  = blockIdx.y >> 2;
    const int n0   = (blockIdx.y & 3) * 128;
    const int t0   = dir ? (TLEN - (seg + 1) * SEGT) : (seg * SEGT);
    const size_t mg0 = (size_t)t0 * BATCH + (size_t)blockIdx.x * 256;   // global A row
    const size_t ml0 = (size_t)blockIdx.x * 256;                         // local out row

    // ---- B tile (128 n-rows x 256 k) hi+lo ----
    {
        const uint4* gh = (const uint4*)(g_wb1h + ((size_t)dir * 512 + n0) * 256);
        const uint4* gl = (const uint4*)(g_wb1l + ((size_t)dir * 512 + n0) * 256);
        for (int i = tid; i < 128 * 32; i += 256) {
            int r = i >> 5, c = i & 31;
            *(uint4*)(sBh + r * BSTR + c * 8) = gh[r * 32 + c];
            *(uint4*)(sBl + r * BSTR + c * 8) = gl[r * 32 + c];
        }
    }

    float acc[4][8][4];
#pragma unroll
    for (int mf = 0; mf < 4; mf++)
#pragma unroll
        for (int j = 0; j < 8; j++)
#pragma unroll
            for (int q = 0; q < 4; q++) acc[mf][j][q] = 0.f;

    for (int kc = 0; kc < 8; kc++) {
        __syncthreads();   // B ready (iter 0) / previous A reads done
        for (int i = tid; i < 256 * 4; i += 256) {
            int r = i >> 2, c = i & 3;
            *(uint4*)(sAh + r * ASTR + c * 8) =
                *(const uint4*)(g_ah + (mg0 + r) * 256 + kc * 32 + c * 8);
            *(uint4*)(sAl + r * ASTR + c * 8) =
                *(const uint4*)(g_al + (mg0 + r) * 256 + kc * 32 + c * 8);
        }
        __syncthreads();

#pragma unroll
        for (int s = 0; s < 2; s++) {
            uint32_t bh[8][2], bl[8][2];
            const int kkb = kc * 32 + s * 16 + 2 * tig;
#pragma unroll
            for (int j = 0; j < 8; j++) {
                const int n = wn + j * 8 + g;
                bh[j][0] = *(const uint32_t*)(sBh + n * BSTR + kkb);
                bh[j][1] = *(const uint32_t*)(sBh + n * BSTR + kkb + 8);
                bl[j][0] = *(const uint32_t*)(sBl + n * BSTR + kkb);
                bl[j][1] = *(const uint32_t*)(sBl + n * BSTR + kkb + 8);
            }
            const int ka = s * 16 + 2 * tig;
#pragma unroll
            for (int mf = 0; mf < 4; mf++) {
                const int mr = wm + mf * 16 + g;
                uint32_t ah0 = *(const uint32_t*)(sAh + mr * ASTR + ka);
                uint32_t ah1 = *(const uint32_t*)(sAh + (mr + 8) * ASTR + ka);
                uint32_t ah2 = *(const uint32_t*)(sAh + mr * ASTR + ka + 8);
                uint32_t ah3 = *(const uint32_t*)(sAh + (mr + 8) * ASTR + ka + 8);
                uint32_t al0 = *(const uint32_t*)(sAl + mr * ASTR + ka);
                uint32_t al1 = *(const uint32_t*)(sAl + (mr + 8) * ASTR + ka);
                uint32_t al2 = *(const uint32_t*)(sAl + mr * ASTR + ka + 8);
                uint32_t al3 = *(const uint32_t*)(sAl + (mr + 8) * ASTR + ka + 8);
#pragma unroll
                for (int j = 0; j < 8; j++) {
                    mma16816(acc[mf][j], ah0, ah1, ah2, ah3, bh[j][0], bh[j][1]);
                    mma16816(acc[mf][j], ah0, ah1, ah2, ah3, bl[j][0], bl[j][1]);
                    mma16816(acc[mf][j], al0, al1, al2, al3, bh[j][0], bh[j][1]);
                }
            }
        }
    }

    // ---- epilogue: +bias, write fp32 xg chunk ----
    float* out = dir ? g_xg1r : g_xg1f;
    const float* bias = g_bias + (2 + dir) * G4 + n0;
#pragma unroll
    for (int mf = 0; mf < 4; mf++) {
#pragma unroll
        for (int j = 0; j < 8; j++) {
            const int col = wn + j * 8 + 2 * tig;
            const size_t row = ml0 + wm + mf * 16 + g;
            float2 bv = *(const float2*)(bias + col);
            float2 v0 = make_float2(acc[mf][j][0] + bv.x, acc[mf][j][1] + bv.y);
            float2 v1 = make_float2(acc[mf][j][2] + bv.x, acc[mf][j][3] + bv.y);
            *(float2*)(out + row * G4 + n0 + col)       = v0;
            *(float2*)(out + (row + 8) * G4 + n0 + col) = v1;
        }
    }
}

// ---------------------------------------------------------------------------
// BiLSTM direction-layer scan. 512 threads, 1 gate/thread, 16 warps/SM.
// L0: full T, K=144 (x fused), writes bf16 hi/lo out0.
// L1: one SEGT segment, K=128, xg-chunk init, h/c carried via g_*state.
// ---------------------------------------------------------------------------
template <bool L0>
__global__ void __launch_bounds__(512, 1) k_lstm(int seg) {
    constexpr int KPAD = L0 ? KPAD0 : KPAD1;
    constexpr int XW   = L0 ? 16 : 0;
    constexpr int KQ   = KPAD / 4;
    constexpr int NT   = L0 ? TLEN : SEGT;

    float* smem = (float*)smem_raw;
    float* zsm = smem;                    // [BT][KPAD]  z = [x | h]
    float* gsm = smem + BT * KPAD;        // [BT][G4]
    float* csm = gsm + BT * G4;           // [BT][HID]

    const int tid = threadIdx.x;
    const int dir = blockIdx.y;
    const int b0  = blockIdx.x * BT;
    const int g0  = tid;                  // one gate per thread

    const float* wpraw = L0 ? (g_wp0 + dir * KPAD0 * G4) : (g_wp1 + dir * KPAD1 * G4);
    const ulonglong2* __restrict__ wp = (const ulonglong2*)wpraw;
    const float bs0 = L0 ? g_bias[dir * G4 + g0] : 0.f;
    const float* __restrict__ xgb = L0 ? nullptr : (dir ? g_xg1r : g_xg1f);
    const int tbase = L0 ? 0 : (dir ? (TLEN - (seg + 1) * SEGT) : (seg * SEGT));

    if (L0 || seg == 0) {
        for (int i = tid; i < BT * KPAD; i += 512) zsm[i] = 0.f;
        for (int i = tid; i < BT * HID;  i += 512) csm[i] = 0.f;
    } else {
        for (int i = tid; i < BT * HID; i += 512) {
            int b = i >> 7, j = i & 127;
            zsm[b * KPAD + XW + j] = g_hstate[(dir * BATCH + b0 + b) * HID + j];
            csm[b * HID + j]       = g_cstate[(dir * BATCH + b0 + b) * HID + j];
        }
    }
    __syncthreads();

    for (int t = 0; t < NT; ++t) {
        // global time index for this step
        const int tg = dir ? (TLEN - 1 - (L0 ? t : (seg * SEGT + t))) : (tbase + t);

        float xa0[BT];
        if (!L0) {
            const int tl = tg - tbase;   // local index in xg chunk, [0, SEGT)
            const float* xg = xgb + ((size_t)tl * BATCH + b0) * G4;
#pragma unroll
            for (int b = 0; b < BT; b++) xa0[b] = xg[b * G4 + g0];
        } else {
            const float4* src = (const float4*)(g_xT + ((size_t)tg * BATCH + b0) * 16);
            for (int i = tid; i < BT * 4; i += 512) {
                int b = i >> 2, c = i & 3;
                *(float4*)&zsm[b * KPAD + c * 4] = src[b * 4 + c];
            }
        }
        __syncthreads();   // x/h ready

        unsigned long long a0[BT];
#pragma unroll
        for (int b = 0; b < BT; b++) a0[b] = L0 ? 0ull : pack2(xa0[b], 0.f);

        // weight stream: prefetch distance 2 (covers L2 latency)
        ulonglong2 wA = wp[g0];
        ulonglong2 wB = (KQ > 1) ? wp[G4 + g0] : wA;
        for (int kk = 0; kk < KQ; kk++) {
            ulonglong2 w0 = wA;
            wA = wB;
            if (kk + 2 < KQ) wB = wp[(kk + 2) * G4 + g0];
            const ulonglong2* zq = (const ulonglong2*)(zsm + kk * 4);
#pragma unroll
            for (int b = 0; b < BT; b++) {
                ulonglong2 zb = zq[b * (KPAD / 4)];   // warp-broadcast LDS.128
                a0[b] = ffma2(zb.x, w0.x, a0[b]);
                a0[b] = ffma2(zb.y, w0.y, a0[b]);
            }
        }

#pragma unroll
        for (int b = 0; b < BT; b++) gsm[b * G4 + g0] = upsum(a0[b]) + bs0;
        __syncthreads();   // gates visible

        // ---- elementwise: one warp per batch row, 4 j's per lane ----
        {
            const int b  = tid >> 5;            // warp id = batch row
            const int j0 = (tid & 31) * 4;
            const float* gb = gsm + b * G4;
            float* cb = csm + b * HID;
            float4 gi4 = *(const float4*)(gb + j0);
            float4 gf4 = *(const float4*)(gb + HID + j0);
            float4 gg4 = *(const float4*)(gb + 2 * HID + j0);
            float4 go4 = *(const float4*)(gb + 3 * HID + j0);
            float4 c4  = *(const float4*)(cb + j0);
            float hv[4];
            c4.x = sigm(gf4.x) * c4.x + sigm(gi4.x) * tanhx(gg4.x);
            c4.y = sigm(gf4.y) * c4.y + sigm(gi4.y) * tanhx(gg4.y);
            c4.z = sigm(gf4.z) * c4.z + sigm(gi4.z) * tanhx(gg4.z);
            c4.w = sigm(gf4.w) * c4.w + sigm(gi4.w) * tanhx(gg4.w);
            hv[0] = sigm(go4.x) * tanhx(c4.x);
            hv[1] = sigm(go4.y) * tanhx(c4.y);
            hv[2] = sigm(go4.z) * tanhx(c4.z);
            hv[3] = sigm(go4.w) * tanhx(c4.w);
            *(float4*)(cb + j0) = c4;
            *(float4*)(zsm + b * KPAD + XW + j0) = make_float4(hv[0], hv[1], hv[2], hv[3]);
            if (L0) {
                __nv_bfloat16 h0 = __float2bfloat16(hv[0]);
                __nv_bfloat16 h1 = __float2bfloat16(hv[1]);
                __nv_bfloat16 h2 = __float2bfloat16(hv[2]);
                __nv_bfloat16 h3 = __float2bfloat16(hv[3]);
                __nv_bfloat162 hb[2] = {{h0, h1}, {h2, h3}};
                __nv_bfloat162 lb[2] = {
                    {__float2bfloat16(hv[0] - __bfloat162float(h0)),
                     __float2bfloat16(hv[1] - __bfloat162float(h1))},
                    {__float2bfloat16(hv[2] - __bfloat162float(h2)),
                     __float2bfloat16(hv[3] - __bfloat162float(h3))}};
                size_t rowoff = ((size_t)tg * BATCH + b0 + b) * 256 + dir * HID + j0;
                *(uint2*)(g_ah + rowoff) = *(uint2*)hb;
                *(uint2*)(g_al + rowoff) = *(uint2*)lb;
            }
        }
        // loop-top __syncthreads orders h-writes before next gate GEMM
    }

    if (!L0) {
        __syncthreads();
        for (int i = tid; i < BT * HID; i += 512) {
            int b = i >> 7, j = i & 127;
            g_hstate[(dir * BATCH + b0 + b) * HID + j] = zsm[b * KPAD + XW + j];
            g_cstate[(dir * BATCH + b0 + b) * HID + j] = csm[b * HID + j];
        }
        if (seg == NSEG - 1) {
            for (int i = tid; i < BT * HID; i += 512) {
                int b = i >> 7, j = i & 127;
                g_final[(size_t)(b0 + b) * 256 + dir * HID + j] = zsm[b * KPAD + XW + j];
            }
        }
    }
}

// ---------------------------------------------------------------------------
// Classifier
// ---------------------------------------------------------------------------
__global__ void k_cls(const float* __restrict__ wc, const float* __restrict__ bc,
                      float* __restrict__ out) {
    int gw   = (blockIdx.x * blockDim.x + threadIdx.x) >> 5;
    int lane = threadIdx.x & 31;
    if (gw >= BATCH) return;
    const float* f = g_final + (size_t)gw * 256;
    float v[8];
#pragma unroll
    for (int i = 0; i < 8; i++) v[i] = f[lane + 32 * i];
#pragma unroll
    for (int nc = 0; nc < NCLS; nc++) {
        float s = 0.f;
#pragma unroll
        for (int i = 0; i < 8; i++) s += v[i] * wc[nc * 256 + lane + 32 * i];
#pragma unroll
        for (int off = 16; off; off >>= 1) s += __shfl_down_sync(0xffffffffu, s, off);
        if (lane == 0) out[gw * NCLS + nc] = s + bc[nc];
    }
}

// ---------------------------------------------------------------------------
extern "C" void kernel_launch(void* const* d_in, const int* in_sizes, int n_in,
                              void* d_out, int out_size) {
    (void)in_sizes; (void)n_in; (void)out_size;
    const float* x = (const float*)d_in[0];

    const int smem0 = (BT * KPAD0 + BT * G4 + BT * HID) * 4;           // 50176
    const int smem1 = (BT * KPAD1 + BT * G4 + BT * HID) * 4;           // 49152
    const int smemX = (2 * 128 * BSTR + 2 * 256 * ASTR) * 2;           // 176128
    (void)cudaFuncSetAttribute(k_lstm<true>,  cudaFuncAttributeMaxDynamicSharedMemorySize, 65536);
    (void)cudaFuncSetAttribute(k_lstm<false>, cudaFuncAttributeMaxDynamicSharedMemorySize, 65536);
    (void)cudaFuncSetAttribute(k_xg1,         cudaFuncAttributeMaxDynamicSharedMemorySize, smemX);

    WPtrs W;
    for (int i = 0; i < 16; i++) W.p[i] = (const float*)d_in[1 + i];

    k_transpose<<<(TLEN * BATCH * 16 + 255) / 256, 256>>>(x);
    k_pack_whh<<<dim3((KPAD0 * G4 + 255) / 256, 4), 256>>>(W);
    k_pack_wb1<<<(2 * G4 * 256 + 255) / 256, 256>>>((const float*)d_in[9], (const float*)d_in[13]);

    k_lstm<true ><<<dim3(BATCH / BT, 2), 512, smem0>>>(0);
    for (int seg = 0; seg < NSEG; seg++) {
        k_xg1<<<dim3((SEGT * BATCH) / 256, 8), 256, smemX>>>(seg);
        k_lstm<false><<<dim3(BATCH / BT, 2), 512, smem1>>>(seg);
    }

    k_cls<<<BATCH / 8, 256>>>((const float*)d_in[17], (const float*)d_in[18], (float*)d_out);
}

// round 11
// speedup vs baseline: 1.0012x; 1.0012x over previous
#include <cuda_runtime.h>
#include <cuda_bf16.h>
#include <cstdint>

#define TLEN  512
#define BATCH 1024
#define HID   128
#define G4    512
#define NCLS  6
#define BT    16
#define KPAD0 144    // 16 (padded x, C=9) + 128 (h)
#define KPAD1 128    // h only (input projection precomputed)
#define SEGT  128    // timesteps per L1 segment
#define NSEG  (TLEN / SEGT)

// ---------------------------------------------------------------------------
// Scratch (device globals; total must stay well under 2 GB — host shadow .bss)
// ---------------------------------------------------------------------------
__device__ __align__(16) float g_xT[(size_t)TLEN * BATCH * 16];              // 32 MB
__device__ __align__(16) __nv_bfloat16 g_ah[(size_t)TLEN * BATCH * 256];     // 256 MB
__device__ __align__(16) __nv_bfloat16 g_al[(size_t)TLEN * BATCH * 256];     // 256 MB
__device__ __align__(16) float g_xg1f[(size_t)SEGT * BATCH * G4];            // 256 MB (fwd chunk)
__device__ __align__(16) float g_xg1r[(size_t)SEGT * BATCH * G4];            // 256 MB (rev chunk)
__device__ __align__(16) float g_hstate[2 * BATCH * HID];                    // 1 MB
__device__ __align__(16) float g_cstate[2 * BATCH * HID];                    // 1 MB
__device__ __align__(16) float g_final[(size_t)BATCH * 256];
__device__ __align__(16) float g_wp0[2 * KPAD0 * G4];
__device__ __align__(16) float g_wp1[2 * KPAD1 * G4];
__device__ __align__(16) __nv_bfloat16 g_wb1h[2 * 512 * 256];                // W_ih_l1 bf16 hi [dir][n][k]
__device__ __align__(16) __nv_bfloat16 g_wb1l[2 * 512 * 256];                // W_ih_l1 bf16 lo
__device__ float g_bias[4 * G4];

// Single dynamic-smem symbol (one type everywhere)
extern __shared__ char smem_raw[];

// ---------------------------------------------------------------------------
// Scalar helpers
// ---------------------------------------------------------------------------
__device__ __forceinline__ unsigned long long ffma2(unsigned long long a,
                                                    unsigned long long b,
                                                    unsigned long long c) {
    unsigned long long d;
    asm("fma.rn.f32x2 %0, %1, %2, %3;" : "=l"(d) : "l"(a), "l"(b), "l"(c));
    return d;
}
__device__ __forceinline__ float upsum(unsigned long long a) {
    float lo, hi;
    asm("mov.b64 {%0, %1}, %2;" : "=f"(lo), "=f"(hi) : "l"(a));
    return lo + hi;
}
__device__ __forceinline__ unsigned long long pack2(float lo, float hi) {
    unsigned long long r;
    asm("mov.b64 %0, {%1, %2};" : "=l"(r) : "f"(lo), "f"(hi));
    return r;
}
__device__ __forceinline__ float sigm(float x) {
    return __fdividef(1.f, 1.f + __expf(-x));
}
__device__ __forceinline__ float tanhx(float x) {
    return __fdividef(2.f, 1.f + __expf(-2.f * x)) - 1.f;
}

// mma.sync m16n8k16 bf16 -> fp32 accumulate (sm_80+, valid on family target)
__device__ __forceinline__ void mma16816(float* c,
                                         uint32_t a0, uint32_t a1, uint32_t a2, uint32_t a3,
                                         uint32_t b0, uint32_t b1) {
    asm volatile(
        "mma.sync.aligned.m16n8k16.row.col.f32.bf16.bf16.f32 "
        "{%0,%1,%2,%3}, {%4,%5,%6,%7}, {%8,%9}, {%0,%1,%2,%3};"
        : "+f"(c[0]), "+f"(c[1]), "+f"(c[2]), "+f"(c[3])
        : "r"(a0), "r"(a1), "r"(a2), "r"(a3), "r"(b0), "r"(b1));
}

// ---------------------------------------------------------------------------
// Prep: transpose x [B,9,T] -> g_xT [T,B,16] (cols 9..15 zero)
// ---------------------------------------------------------------------------
__global__ void k_transpose(const float* __restrict__ x) {
    size_t o = (size_t)blockIdx.x * blockDim.x + threadIdx.x;
    if (o >= (size_t)TLEN * BATCH * 16) return;
    int c = (int)(o & 15);
    size_t tb = o >> 4;
    int b = (int)(tb % BATCH);
    int t = (int)(tb / BATCH);
    g_xT[o] = (c < 9) ? x[((size_t)b * 9 + c) * TLEN + t] : 0.f;
}

// ---------------------------------------------------------------------------
// Pack scan weights, quad-interleaved wp[kk][g][4]; bias sums.
// which: 0=l0f 1=l0r (K=144), 2=l1f 3=l1r (K=128, h only)
// ---------------------------------------------------------------------------
struct WPtrs { const float* p[16]; };

__global__ void k_pack_whh(WPtrs W) {
    const int which = blockIdx.y;
    const float* wih = W.p[which * 4 + 0];
    const float* whh = W.p[which * 4 + 1];
    const float* bih = W.p[which * 4 + 2];
    const float* bhh = W.p[which * 4 + 3];
    const int kpad = (which < 2) ? KPAD0 : KPAD1;
    int o = blockIdx.x * blockDim.x + threadIdx.x;
    if (o < G4) g_bias[which * G4 + o] = bih[o] + bhh[o];
    if (o >= kpad * G4) return;
    int kk = o / (G4 * 4);
    int rem = o % (G4 * 4);
    int g = rem / 4, j = rem % 4;
    int k = kk * 4 + j;
    float v = 0.f;
    if (which < 2) {
        if (k < 9)                      v = wih[g * 9 + k];
        else if (k >= 16 && k < 144)    v = whh[g * HID + (k - 16)];
        g_wp0[which * KPAD0 * G4 + o] = v;
    } else {
        v = whh[g * HID + k];
        g_wp1[(which - 2) * KPAD1 * G4 + o] = v;
    }
}

// ---------------------------------------------------------------------------
// Pack W_ih_l1 fp32 -> bf16 hi/lo, plain [dir][512 n][256 k] row-major
// ---------------------------------------------------------------------------
__global__ void k_pack_wb1(const float* __restrict__ wf, const float* __restrict__ wr) {
    int o = blockIdx.x * blockDim.x + threadIdx.x;
    if (o >= 2 * G4 * 256) return;
    int dir = o / (G4 * 256);
    int rem = o % (G4 * 256);
    const float* w = dir ? wr : wf;
    float v = w[rem];
    __nv_bfloat16 h = __float2bfloat16(v);
    __nv_bfloat16 l = __float2bfloat16(v - __bfloat162float(h));
    g_wb1h[o] = h;
    g_wb1l[o] = l;
}

// ---------------------------------------------------------------------------
// xg1 chunk: for segment seg, per dir, compute xg = out0 @ W_ih_l1^T + bias
// over SEGT timesteps. Grid (512, 8): y = dir*4 + ntile. Block 256 thr =
// 8 warps (4m x 2n), tile 256m x 128n x K256, atom m16n8k16, bf16 3-split.
// ---------------------------------------------------------------------------
#define BSTR 264   // B smem row stride (bf16)
#define ASTR 40    // A smem row stride (bf16)

__global__ void __launch_bounds__(256, 1) k_xg1(int seg) {
    __nv_bfloat16* sBh = (__nv_bfloat16*)smem_raw;
    __nv_bfloat16* sBl = sBh + 128 * BSTR;
    __nv_bfloat16* sAh = sBl + 128 * BSTR;
    __nv_bfloat16* sAl = sAh + 256 * ASTR;

    const int tid  = threadIdx.x;
    const int wid  = tid >> 5, lane = tid & 31;
    const int g    = lane >> 2, tig = lane & 3;
    const int wm   = (wid & 3) * 64;
    const int wn   = (wid >> 2) * 64;
    const int dir  = blockIdx.y >> 2;
    const int n0   = (blockIdx.y & 3) * 128;
    const int t0   = dir ? (TLEN - (seg + 1) * SEGT) : (seg * SEGT);
    const size_t mg0 = (size_t)t0 * BATCH + (size_t)blockIdx.x * 256;   // global A row
    const size_t ml0 = (size_t)blockIdx.x * 256;                         // local out row

    // ---- B tile (128 n-rows x 256 k) hi+lo ----
    {
        const uint4* gh = (const uint4*)(g_wb1h + ((size_t)dir * 512 + n0) * 256);
        const uint4* gl = (const uint4*)(g_wb1l + ((size_t)dir * 512 + n0) * 256);
        for (int i = tid; i < 128 * 32; i += 256) {
            int r = i >> 5, c = i & 31;
            *(uint4*)(sBh + r * BSTR + c * 8) = gh[r * 32 + c];
            *(uint4*)(sBl + r * BSTR + c * 8) = gl[r * 32 + c];
        }
    }

    float acc[4][8][4];
#pragma unroll
    for (int mf = 0; mf < 4; mf++)
#pragma unroll
        for (int j = 0; j < 8; j++)
#pragma unroll
            for (int q = 0; q < 4; q++) acc[mf][j][q] = 0.f;

    for (int kc = 0; kc < 8; kc++) {
        __syncthreads();   // B ready (iter 0) / previous A reads done
        for (int i = tid; i < 256 * 4; i += 256) {
            int r = i >> 2, c = i & 3;
            *(uint4*)(sAh + r * ASTR + c * 8) =
                *(const uint4*)(g_ah + (mg0 + r) * 256 + kc * 32 + c * 8);
            *(uint4*)(sAl + r * ASTR + c * 8) =
                *(const uint4*)(g_al + (mg0 + r) * 256 + kc * 32 + c * 8);
        }
        __syncthreads();

#pragma unroll
        for (int s = 0; s < 2; s++) {
            uint32_t bh[8][2], bl[8][2];
            const int kkb = kc * 32 + s * 16 + 2 * tig;
#pragma unroll
            for (int j = 0; j < 8; j++) {
                const int n = wn + j * 8 + g;
                bh[j][0] = *(const uint32_t*)(sBh + n * BSTR + kkb);
                bh[j][1] = *(const uint32_t*)(sBh + n * BSTR + kkb + 8);
                bl[j][0] = *(const uint32_t*)(sBl + n * BSTR + kkb);
                bl[j][1] = *(const uint32_t*)(sBl + n * BSTR + kkb + 8);
            }
            const int ka = s * 16 + 2 * tig;
#pragma unroll
            for (int mf = 0; mf < 4; mf++) {
                const int mr = wm + mf * 16 + g;
                uint32_t ah0 = *(const uint32_t*)(sAh + mr * ASTR + ka);
                uint32_t ah1 = *(const uint32_t*)(sAh + (mr + 8) * ASTR + ka);
                uint32_t ah2 = *(const uint32_t*)(sAh + mr * ASTR + ka + 8);
                uint32_t ah3 = *(const uint32_t*)(sAh + (mr + 8) * ASTR + ka + 8);
                uint32_t al0 = *(const uint32_t*)(sAl + mr * ASTR + ka);
                uint32_t al1 = *(const uint32_t*)(sAl + (mr + 8) * ASTR + ka);
                uint32_t al2 = *(const uint32_t*)(sAl + mr * ASTR + ka + 8);
                uint32_t al3 = *(const uint32_t*)(sAl + (mr + 8) * ASTR + ka + 8);
#pragma unroll
                for (int j = 0; j < 8; j++) {
                    mma16816(acc[mf][j], ah0, ah1, ah2, ah3, bh[j][0], bh[j][1]);
                    mma16816(acc[mf][j], ah0, ah1, ah2, ah3, bl[j][0], bl[j][1]);
                    mma16816(acc[mf][j], al0, al1, al2, al3, bh[j][0], bh[j][1]);
                }
            }
        }
    }

    // ---- epilogue: +bias, write fp32 xg chunk ----
    float* out = dir ? g_xg1r : g_xg1f;
    const float* bias = g_bias + (2 + dir) * G4 + n0;
#pragma unroll
    for (int mf = 0; mf < 4; mf++) {
#pragma unroll
        for (int j = 0; j < 8; j++) {
            const int col = wn + j * 8 + 2 * tig;
            const size_t row = ml0 + wm + mf * 16 + g;
            float2 bv = *(const float2*)(bias + col);
            float2 v0 = make_float2(acc[mf][j][0] + bv.x, acc[mf][j][1] + bv.y);
            float2 v1 = make_float2(acc[mf][j][2] + bv.x, acc[mf][j][3] + bv.y);
            *(float2*)(out + row * G4 + n0 + col)       = v0;
            *(float2*)(out + (row + 8) * G4 + n0 + col) = v1;
        }
    }
}

// ---------------------------------------------------------------------------
// BiLSTM direction-layer scan. 512 threads, 1 gate/thread, 16 warps/SM.
// L0: full T, K=144 (x fused), writes bf16 hi/lo out0.
// L1: one SEGT segment, K=128, xg-chunk init, h/c carried via g_*state.
// ---------------------------------------------------------------------------
template <bool L0>
__global__ void __launch_bounds__(512, 1) k_lstm(int seg) {
    constexpr int KPAD = L0 ? KPAD0 : KPAD1;
    constexpr int XW   = L0 ? 16 : 0;
    constexpr int KQ   = KPAD / 4;
    constexpr int NT   = L0 ? TLEN : SEGT;

    float* smem = (float*)smem_raw;
    float* zsm = smem;                    // [BT][KPAD]  z = [x | h]
    float* gsm = smem + BT * KPAD;        // [BT][G4]
    float* csm = gsm + BT * G4;           // [BT][HID]

    const int tid = threadIdx.x;
    const int dir = blockIdx.y;
    const int b0  = blockIdx.x * BT;
    const int g0  = tid;                  // one gate per thread

    const float* wpraw = L0 ? (g_wp0 + dir * KPAD0 * G4) : (g_wp1 + dir * KPAD1 * G4);
    const ulonglong2* __restrict__ wp = (const ulonglong2*)wpraw;
    const float bs0 = L0 ? g_bias[dir * G4 + g0] : 0.f;
    const float* __restrict__ xgb = L0 ? nullptr : (dir ? g_xg1r : g_xg1f);
    const int tbase = L0 ? 0 : (dir ? (TLEN - (seg + 1) * SEGT) : (seg * SEGT));

    if (L0 || seg == 0) {
        for (int i = tid; i < BT * KPAD; i += 512) zsm[i] = 0.f;
        for (int i = tid; i < BT * HID;  i += 512) csm[i] = 0.f;
    } else {
        for (int i = tid; i < BT * HID; i += 512) {
            int b = i >> 7, j = i & 127;
            zsm[b * KPAD + XW + j] = g_hstate[(dir * BATCH + b0 + b) * HID + j];
            csm[b * HID + j]       = g_cstate[(dir * BATCH + b0 + b) * HID + j];
        }
    }
    __syncthreads();

    for (int t = 0; t < NT; ++t) {
        // global time index for this step
        const int tg = dir ? (TLEN - 1 - (L0 ? t : (seg * SEGT + t))) : (tbase + t);

        float xa0[BT];
        if (!L0) {
            const int tl = tg - tbase;   // local index in xg chunk, [0, SEGT)
            const float* xg = xgb + ((size_t)tl * BATCH + b0) * G4;
#pragma unroll
            for (int b = 0; b < BT; b++) xa0[b] = xg[b * G4 + g0];
        } else {
            const float4* src = (const float4*)(g_xT + ((size_t)tg * BATCH + b0) * 16);
            for (int i = tid; i < BT * 4; i += 512) {
                int b = i >> 2, c = i & 3;
                *(float4*)&zsm[b * KPAD + c * 4] = src[b * 4 + c];
            }
        }
        __syncthreads();   // x/h ready

        unsigned long long a0[BT];
#pragma unroll
        for (int b = 0; b < BT; b++) a0[b] = L0 ? 0ull : pack2(xa0[b], 0.f);

        // weight stream: prefetch distance 2 (covers L2 latency)
        ulonglong2 wA = wp[g0];
        ulonglong2 wB = (KQ > 1) ? wp[G4 + g0] : wA;
        for (int kk = 0; kk < KQ; kk++) {
            ulonglong2 w0 = wA;
            wA = wB;
            if (kk + 2 < KQ) wB = wp[(kk + 2) * G4 + g0];
            const ulonglong2* zq = (const ulonglong2*)(zsm + kk * 4);
#pragma unroll
            for (int b = 0; b < BT; b++) {
                ulonglong2 zb = zq[b * (KPAD / 4)];   // warp-broadcast LDS.128
                a0[b] = ffma2(zb.x, w0.x, a0[b]);
                a0[b] = ffma2(zb.y, w0.y, a0[b]);
            }
        }

#pragma unroll
        for (int b = 0; b < BT; b++) gsm[b * G4 + g0] = upsum(a0[b]) + bs0;
        __syncthreads();   // gates visible

        // ---- elementwise: one warp per batch row, 4 j's per lane ----
        {
            const int b  = tid >> 5;            // warp id = batch row
            const int j0 = (tid & 31) * 4;
            const float* gb = gsm + b * G4;
            float* cb = csm + b * HID;
            float4 gi4 = *(const float4*)(gb + j0);
            float4 gf4 = *(const float4*)(gb + HID + j0);
            float4 gg4 = *(const float4*)(gb + 2 * HID + j0);
            float4 go4 = *(const float4*)(gb + 3 * HID + j0);
            float4 c4  = *(const float4*)(cb + j0);
            float hv[4];
            c4.x = sigm(gf4.x) * c4.x + sigm(gi4.x) * tanhx(gg4.x);
            c4.y = sigm(gf4.y) * c4.y + sigm(gi4.y) * tanhx(gg4.y);
            c4.z = sigm(gf4.z) * c4.z + sigm(gi4.z) * tanhx(gg4.z);
            c4.w = sigm(gf4.w) * c4.w + sigm(gi4.w) * tanhx(gg4.w);
            hv[0] = sigm(go4.x) * tanhx(c4.x);
            hv[1] = sigm(go4.y) * tanhx(c4.y);
            hv[2] = sigm(go4.z) * tanhx(c4.z);
            hv[3] = sigm(go4.w) * tanhx(c4.w);
            *(float4*)(cb + j0) = c4;
            *(float4*)(zsm + b * KPAD + XW + j0) = make_float4(hv[0], hv[1], hv[2], hv[3]);
            if (L0) {
                __nv_bfloat16 h0 = __float2bfloat16(hv[0]);
                __nv_bfloat16 h1 = __float2bfloat16(hv[1]);
                __nv_bfloat16 h2 = __float2bfloat16(hv[2]);
                __nv_bfloat16 h3 = __float2bfloat16(hv[3]);
                __nv_bfloat162 hb[2] = {{h0, h1}, {h2, h3}};
                __nv_bfloat162 lb[2] = {
                    {__float2bfloat16(hv[0] - __bfloat162float(h0)),
                     __float2bfloat16(hv[1] - __bfloat162float(h1))},
                    {__float2bfloat16(hv[2] - __bfloat162float(h2)),
                     __float2bfloat16(hv[3] - __bfloat162float(h3))}};
                size_t rowoff = ((size_t)tg * BATCH + b0 + b) * 256 + dir * HID + j0;
                *(uint2*)(g_ah + rowoff) = *(uint2*)hb;
                *(uint2*)(g_al + rowoff) = *(uint2*)lb;
            }
        }
        // loop-top __syncthreads orders h-writes before next gate GEMM
    }

    if (!L0) {
        __syncthreads();
        for (int i = tid; i < BT * HID; i += 512) {
            int b = i >> 7, j = i & 127;
            g_hstate[(dir * BATCH + b0 + b) * HID + j] = zsm[b * KPAD + XW + j];
            g_cstate[(dir * BATCH + b0 + b) * HID + j] = csm[b * HID + j];
        }
        if (seg == NSEG - 1) {
            for (int i = tid; i < BT * HID; i += 512) {
                int b = i >> 7, j = i & 127;
                g_final[(size_t)(b0 + b) * 256 + dir * HID + j] = zsm[b * KPAD + XW + j];
            }
        }
    }
}

// ---------------------------------------------------------------------------
// Classifier
// ---------------------------------------------------------------------------
__global__ void k_cls(const float* __restrict__ wc, const float* __restrict__ bc,
                      float* __restrict__ out) {
    int gw   = (blockIdx.x * blockDim.x + threadIdx.x) >> 5;
    int lane = threadIdx.x & 31;
    if (gw >= BATCH) return;
    const float* f = g_final + (size_t)gw * 256;
    float v[8];
#pragma unroll
    for (int i = 0; i < 8; i++) v[i] = f[lane + 32 * i];
#pragma unroll
    for (int nc = 0; nc < NCLS; nc++) {
        float s = 0.f;
#pragma unroll
        for (int i = 0; i < 8; i++) s += v[i] * wc[nc * 256 + lane + 32 * i];
#pragma unroll
        for (int off = 16; off; off >>= 1) s += __shfl_down_sync(0xffffffffu, s, off);
        if (lane == 0) out[gw * NCLS + nc] = s + bc[nc];
    }
}

// ---------------------------------------------------------------------------
extern "C" void kernel_launch(void* const* d_in, const int* in_sizes, int n_in,
                              void* d_out, int out_size) {
    (void)in_sizes; (void)n_in; (void)out_size;
    const float* x = (const float*)d_in[0];

    const int smem0 = (BT * KPAD0 + BT * G4 + BT * HID) * 4;           // 50176
    const int smem1 = (BT * KPAD1 + BT * G4 + BT * HID) * 4;           // 49152
    const int smemX = (2 * 128 * BSTR + 2 * 256 * ASTR) * 2;           // 176128
    (void)cudaFuncSetAttribute(k_lstm<true>,  cudaFuncAttributeMaxDynamicSharedMemorySize, 65536);
    (void)cudaFuncSetAttribute(k_lstm<false>, cudaFuncAttributeMaxDynamicSharedMemorySize, 65536);
    (void)cudaFuncSetAttribute(k_xg1,         cudaFuncAttributeMaxDynamicSharedMemorySize, smemX);

    WPtrs W;
    for (int i = 0; i < 16; i++) W.p[i] = (const float*)d_in[1 + i];

    k_transpose<<<(TLEN * BATCH * 16 + 255) / 256, 256>>>(x);
    k_pack_whh<<<dim3((KPAD0 * G4 + 255) / 256, 4), 256>>>(W);
    k_pack_wb1<<<(2 * G4 * 256 + 255) / 256, 256>>>((const float*)d_in[9], (const float*)d_in[13]);

    k_lstm<true ><<<dim3(BATCH / BT, 2), 512, smem0>>>(0);
    for (int seg = 0; seg < NSEG; seg++) {
        k_xg1<<<dim3((SEGT * BATCH) / 256, 8), 256, smemX>>>(seg);
        k_lstm<false><<<dim3(BATCH / BT, 2), 512, smem1>>>(seg);
    }

    k_cls<<<BATCH / 8, 256>>>((const float*)d_in[17], (const float*)d_in[18], (float*)d_out);
}

// round 12
// speedup vs baseline: 1.1098x; 1.1085x over previous
#include <cuda_runtime.h>
#include <cuda_bf16.h>
#include <cstdint>

#define TLEN  512
#define BATCH 1024
#define HID   128
#define G4    512
#define NCLS  6
#define BT    16
#define KPAD0 144    // 16 (padded x, C=9) + 128 (h)
#define KPAD1 128    // h only (input projection precomputed)
#define SEGT  128    // timesteps per L1 segment
#define NSEG  (TLEN / SEGT)

// ---------------------------------------------------------------------------
// Scratch (device globals; total must stay well under 2 GB — host shadow .bss)
// ---------------------------------------------------------------------------
__device__ __align__(16) float g_xT[(size_t)TLEN * BATCH * 16];              // 32 MB
__device__ __align__(16) __nv_bfloat16 g_ah[(size_t)TLEN * BATCH * 256];     // 256 MB
__device__ __align__(16) __nv_bfloat16 g_al[(size_t)TLEN * BATCH * 256];     // 256 MB
__device__ __align__(16) float g_xg1f[(size_t)SEGT * BATCH * G4];            // 256 MB (fwd chunk)
__device__ __align__(16) float g_xg1r[(size_t)SEGT * BATCH * G4];            // 256 MB (rev chunk)
__device__ __align__(16) float g_hstate[2 * BATCH * HID];                    // 1 MB
__device__ __align__(16) float g_cstate[2 * BATCH * HID];                    // 1 MB
__device__ __align__(16) float g_final[(size_t)BATCH * 256];
__device__ __align__(16) float g_wp0[2 * KPAD0 * G4];
__device__ __align__(16) float g_wp1[2 * KPAD1 * G4];
__device__ __align__(16) __nv_bfloat16 g_wb1h[2 * 512 * 256];                // W_ih_l1 bf16 hi [dir][n][k]
__device__ __align__(16) __nv_bfloat16 g_wb1l[2 * 512 * 256];                // W_ih_l1 bf16 lo
__device__ float g_bias[4 * G4];

// Single dynamic-smem symbol (one type everywhere)
extern __shared__ char smem_raw[];

// ---------------------------------------------------------------------------
// Scalar helpers
// ---------------------------------------------------------------------------
__device__ __forceinline__ unsigned long long ffma2(unsigned long long a,
                                                    unsigned long long b,
                                                    unsigned long long c) {
    unsigned long long d;
    asm("fma.rn.f32x2 %0, %1, %2, %3;" : "=l"(d) : "l"(a), "l"(b), "l"(c));
    return d;
}
__device__ __forceinline__ float upsum(unsigned long long a) {
    float lo, hi;
    asm("mov.b64 {%0, %1}, %2;" : "=f"(lo), "=f"(hi) : "l"(a));
    return lo + hi;
}
__device__ __forceinline__ unsigned long long pack2(float lo, float hi) {
    unsigned long long r;
    asm("mov.b64 %0, {%1, %2};" : "=l"(r) : "f"(lo), "f"(hi));
    return r;
}
__device__ __forceinline__ float sigm(float x) {
    return __fdividef(1.f, 1.f + __expf(-x));
}
__device__ __forceinline__ float tanhx(float x) {
    return __fdividef(2.f, 1.f + __expf(-2.f * x)) - 1.f;
}
__device__ __forceinline__ uint32_t smem_u32(const void* p) {
    uint32_t a;
    asm("{ .reg .u64 t; cvta.to.shared.u64 t, %1; cvt.u32.u64 %0, t; }" : "=r"(a) : "l"(p));
    return a;
}
__device__ __forceinline__ void cp16(uint32_t saddr, const void* gptr) {
    asm volatile("cp.async.cg.shared.global [%0], [%1], 16;"
                 :: "r"(saddr), "l"(gptr) : "memory");
}

// mma.sync m16n8k16 bf16 -> fp32 accumulate (sm_80+, valid on family target)
__device__ __forceinline__ void mma16816(float* c,
                                         uint32_t a0, uint32_t a1, uint32_t a2, uint32_t a3,
                                         uint32_t b0, uint32_t b1) {
    asm volatile(
        "mma.sync.aligned.m16n8k16.row.col.f32.bf16.bf16.f32 "
        "{%0,%1,%2,%3}, {%4,%5,%6,%7}, {%8,%9}, {%0,%1,%2,%3};"
        : "+f"(c[0]), "+f"(c[1]), "+f"(c[2]), "+f"(c[3])
        : "r"(a0), "r"(a1), "r"(a2), "r"(a3), "r"(b0), "r"(b1));
}

// ---------------------------------------------------------------------------
// Prep: transpose x [B,9,T] -> g_xT [T,B,16] (cols 9..15 zero)
// ---------------------------------------------------------------------------
__global__ void k_transpose(const float* __restrict__ x) {
    size_t o = (size_t)blockIdx.x * blockDim.x + threadIdx.x;
    if (o >= (size_t)TLEN * BATCH * 16) return;
    int c = (int)(o & 15);
    size_t tb = o >> 4;
    int b = (int)(tb % BATCH);
    int t = (int)(tb / BATCH);
    g_xT[o] = (c < 9) ? x[((size_t)b * 9 + c) * TLEN + t] : 0.f;
}

// ---------------------------------------------------------------------------
// Pack scan weights, quad-interleaved wp[kk][g][4]; bias sums.
// which: 0=l0f 1=l0r (K=144), 2=l1f 3=l1r (K=128, h only)
// ---------------------------------------------------------------------------
struct WPtrs { const float* p[16]; };

__global__ void k_pack_whh(WPtrs W) {
    const int which = blockIdx.y;
    const float* wih = W.p[which * 4 + 0];
    const float* whh = W.p[which * 4 + 1];
    const float* bih = W.p[which * 4 + 2];
    const float* bhh = W.p[which * 4 + 3];
    const int kpad = (which < 2) ? KPAD0 : KPAD1;
    int o = blockIdx.x * blockDim.x + threadIdx.x;
    if (o < G4) g_bias[which * G4 + o] = bih[o] + bhh[o];
    if (o >= kpad * G4) return;
    int kk = o / (G4 * 4);
    int rem = o % (G4 * 4);
    int g = rem / 4, j = rem % 4;
    int k = kk * 4 + j;
    float v = 0.f;
    if (which < 2) {
        if (k < 9)                      v = wih[g * 9 + k];
        else if (k >= 16 && k < 144)    v = whh[g * HID + (k - 16)];
        g_wp0[which * KPAD0 * G4 + o] = v;
    } else {
        v = whh[g * HID + k];
        g_wp1[(which - 2) * KPAD1 * G4 + o] = v;
    }
}

// ---------------------------------------------------------------------------
// Pack W_ih_l1 fp32 -> bf16 hi/lo, plain [dir][512 n][256 k] row-major
// ---------------------------------------------------------------------------
__global__ void k_pack_wb1(const float* __restrict__ wf, const float* __restrict__ wr) {
    int o = blockIdx.x * blockDim.x + threadIdx.x;
    if (o >= 2 * G4 * 256) return;
    int dir = o / (G4 * 256);
    int rem = o % (G4 * 256);
    const float* w = dir ? wr : wf;
    float v = w[rem];
    __nv_bfloat16 h = __float2bfloat16(v);
    __nv_bfloat16 l = __float2bfloat16(v - __bfloat162float(h));
    g_wb1h[o] = h;
    g_wb1l[o] = l;
}

// ---------------------------------------------------------------------------
// xg1 chunk GEMM: xg = out0 @ W_ih_l1^T + bias over SEGT timesteps.
// Grid (1024, 8): y = dir*4 + ntile. Block 256 thr = 8 warps (2m x 4n),
// block tile 128m x 128n x K256 in 32-chunks, cp.async double-buffered,
// occupancy 2. bf16 3-split (AhBh + AhBl + AlBh).
// ---------------------------------------------------------------------------
#define XSTR   40                      // smem row stride (bf16)
#define XMAT   (128 * XSTR)            // one matrix tile (bf16 elems)
#define XSTAGE (4 * XMAT)              // Ah, Al, Bh, Bl
#define XSMEM  (2 * XSTAGE * 2)        // bytes: 2 stages

__global__ void __launch_bounds__(256, 2) k_xg1(int seg) {
    __nv_bfloat16* sm = (__nv_bfloat16*)smem_raw;
    const uint32_t sbase = smem_u32(sm);

    const int tid  = threadIdx.x;
    const int wid  = tid >> 5, lane = tid & 31;
    const int g    = lane >> 2, tig = lane & 3;
    const int wm   = (wid & 1) * 64;
    const int wn   = (wid >> 1) * 32;
    const int dir  = blockIdx.y >> 2;
    const int n0   = (blockIdx.y & 3) * 128;
    const int t0   = dir ? (TLEN - (seg + 1) * SEGT) : (seg * SEGT);
    const size_t mg0 = (size_t)t0 * BATCH + (size_t)blockIdx.x * 128;   // global A row
    const size_t ml0 = (size_t)blockIdx.x * 128;                        // local out row

    const __nv_bfloat16* gBh = g_wb1h + ((size_t)dir * 512 + n0) * 256;
    const __nv_bfloat16* gBl = g_wb1l + ((size_t)dir * 512 + n0) * 256;

    // stage loader: 4 matrices x 128 rows x 32 k (4 x 16B per row) = 2048 cp16
    auto load_stage = [&](int kc, int stage) {
        const uint32_t sb = sbase + (uint32_t)stage * XSTAGE * 2;
#pragma unroll
        for (int j = 0; j < 8; j++) {
            int i = tid + 256 * j;
            int mat = i >> 9;
            int r   = (i >> 2) & 127;
            int c   = i & 3;
            const __nv_bfloat16* gp;
            if (mat == 0)      gp = g_ah + (mg0 + r) * 256 + kc * 32 + c * 8;
            else if (mat == 1) gp = g_al + (mg0 + r) * 256 + kc * 32 + c * 8;
            else if (mat == 2) gp = gBh + (size_t)r * 256 + kc * 32 + c * 8;
            else               gp = gBl + (size_t)r * 256 + kc * 32 + c * 8;
            uint32_t sa = sb + (uint32_t)(mat * XMAT + r * XSTR + c * 8) * 2;
            cp16(sa, gp);
        }
        asm volatile("cp.async.commit_group;" ::: "memory");
    };

    float acc[4][4][4];
#pragma unroll
    for (int mf = 0; mf < 4; mf++)
#pragma unroll
        for (int nf = 0; nf < 4; nf++)
#pragma unroll
            for (int q = 0; q < 4; q++) acc[mf][nf][q] = 0.f;

    load_stage(0, 0);

    for (int kc = 0; kc < 8; kc++) {
        if (kc + 1 < 8) {
            load_stage(kc + 1, (kc + 1) & 1);
            asm volatile("cp.async.wait_group 1;" ::: "memory");
        } else {
            asm volatile("cp.async.wait_group 0;" ::: "memory");
        }
        __syncthreads();   // stage kc visible to all warps

        const __nv_bfloat16* sAh = sm + (kc & 1) * XSTAGE;
        const __nv_bfloat16* sAl = sAh + XMAT;
        const __nv_bfloat16* sBh = sAh + 2 * XMAT;
        const __nv_bfloat16* sBl = sAh + 3 * XMAT;

#pragma unroll
        for (int s = 0; s < 2; s++) {
            const int kb = s * 16 + 2 * tig;
            uint32_t bh[4][2], bl[4][2];
#pragma unroll
            for (int nf = 0; nf < 4; nf++) {
                const int n = wn + nf * 8 + g;
                bh[nf][0] = *(const uint32_t*)(sBh + n * XSTR + kb);
                bh[nf][1] = *(const uint32_t*)(sBh + n * XSTR + kb + 8);
                bl[nf][0] = *(const uint32_t*)(sBl + n * XSTR + kb);
                bl[nf][1] = *(const uint32_t*)(sBl + n * XSTR + kb + 8);
            }
#pragma unroll
            for (int mf = 0; mf < 4; mf++) {
                const int mr = wm + mf * 16 + g;
                uint32_t ah0 = *(const uint32_t*)(sAh + mr * XSTR + kb);
                uint32_t ah1 = *(const uint32_t*)(sAh + (mr + 8) * XSTR + kb);
                uint32_t ah2 = *(const uint32_t*)(sAh + mr * XSTR + kb + 8);
                uint32_t ah3 = *(const uint32_t*)(sAh + (mr + 8) * XSTR + kb + 8);
                uint32_t al0 = *(const uint32_t*)(sAl + mr * XSTR + kb);
                uint32_t al1 = *(const uint32_t*)(sAl + (mr + 8) * XSTR + kb);
                uint32_t al2 = *(const uint32_t*)(sAl + mr * XSTR + kb + 8);
                uint32_t al3 = *(const uint32_t*)(sAl + (mr + 8) * XSTR + kb + 8);
#pragma unroll
                for (int nf = 0; nf < 4; nf++) {
                    mma16816(acc[mf][nf], ah0, ah1, ah2, ah3, bh[nf][0], bh[nf][1]);
                    mma16816(acc[mf][nf], ah0, ah1, ah2, ah3, bl[nf][0], bl[nf][1]);
                    mma16816(acc[mf][nf], al0, al1, al2, al3, bh[nf][0], bh[nf][1]);
                }
            }
        }
        __syncthreads();   // all warps done with stage kc before it is reloaded
    }

    // ---- epilogue: +bias, write fp32 xg chunk ----
    float* out = dir ? g_xg1r : g_xg1f;
    const float* bias = g_bias + (2 + dir) * G4 + n0;
#pragma unroll
    for (int mf = 0; mf < 4; mf++) {
#pragma unroll
        for (int nf = 0; nf < 4; nf++) {
            const int col = wn + nf * 8 + 2 * tig;
            const size_t row = ml0 + wm + mf * 16 + g;
            float2 bv = *(const float2*)(bias + col);
            float2 v0 = make_float2(acc[mf][nf][0] + bv.x, acc[mf][nf][1] + bv.y);
            float2 v1 = make_float2(acc[mf][nf][2] + bv.x, acc[mf][nf][3] + bv.y);
            *(float2*)(out + row * G4 + n0 + col)       = v0;
            *(float2*)(out + (row + 8) * G4 + n0 + col) = v1;
        }
    }
}

// ---------------------------------------------------------------------------
// BiLSTM direction-layer scan. 512 threads, 1 gate/thread, 16 warps/SM.
// L0: full T, K=144 (x fused), writes bf16 hi/lo out0.
// L1: one SEGT segment, K=128, xg-chunk init, h/c carried via g_*state.
// ---------------------------------------------------------------------------
template <bool L0>
__global__ void __launch_bounds__(512, 1) k_lstm(int seg) {
    constexpr int KPAD = L0 ? KPAD0 : KPAD1;
    constexpr int XW   = L0 ? 16 : 0;
    constexpr int KQ   = KPAD / 4;
    constexpr int NT   = L0 ? TLEN : SEGT;

    float* smem = (float*)smem_raw;
    float* zsm = smem;                    // [BT][KPAD]  z = [x | h]
    float* gsm = smem + BT * KPAD;        // [BT][G4]
    float* csm = gsm + BT * G4;           // [BT][HID]

    const int tid = threadIdx.x;
    const int dir = blockIdx.y;
    const int b0  = blockIdx.x * BT;
    const int g0  = tid;                  // one gate per thread

    const float* wpraw = L0 ? (g_wp0 + dir * KPAD0 * G4) : (g_wp1 + dir * KPAD1 * G4);
    const ulonglong2* __restrict__ wp = (const ulonglong2*)wpraw;
    const float bs0 = L0 ? g_bias[dir * G4 + g0] : 0.f;
    const float* __restrict__ xgb = L0 ? nullptr : (dir ? g_xg1r : g_xg1f);
    const int tbase = L0 ? 0 : (dir ? (TLEN - (seg + 1) * SEGT) : (seg * SEGT));

    if (L0 || seg == 0) {
        for (int i = tid; i < BT * KPAD; i += 512) zsm[i] = 0.f;
        for (int i = tid; i < BT * HID;  i += 512) csm[i] = 0.f;
    } else {
        for (int i = tid; i < BT * HID; i += 512) {
            int b = i >> 7, j = i & 127;
            zsm[b * KPAD + XW + j] = g_hstate[(dir * BATCH + b0 + b) * HID + j];
            csm[b * HID + j]       = g_cstate[(dir * BATCH + b0 + b) * HID + j];
        }
    }
    __syncthreads();

    for (int t = 0; t < NT; ++t) {
        // global time index for this step
        const int tg = dir ? (TLEN - 1 - (L0 ? t : (seg * SEGT + t))) : (tbase + t);

        float xa0[BT];
        if (!L0) {
            const int tl = tg - tbase;   // local index in xg chunk, [0, SEGT)
            const float* xg = xgb + ((size_t)tl * BATCH + b0) * G4;
#pragma unroll
            for (int b = 0; b < BT; b++) xa0[b] = xg[b * G4 + g0];
        } else {
            const float4* src = (const float4*)(g_xT + ((size_t)tg * BATCH + b0) * 16);
            for (int i = tid; i < BT * 4; i += 512) {
                int b = i >> 2, c = i & 3;
                *(float4*)&zsm[b * KPAD + c * 4] = src[b * 4 + c];
            }
        }
        __syncthreads();   // x/h ready

        unsigned long long a0[BT];
#pragma unroll
        for (int b = 0; b < BT; b++) a0[b] = L0 ? 0ull : pack2(xa0[b], 0.f);

        // weight stream: prefetch distance 2 (covers L2 latency)
        ulonglong2 wA = wp[g0];
        ulonglong2 wB = (KQ > 1) ? wp[G4 + g0] : wA;
        for (int kk = 0; kk < KQ; kk++) {
            ulonglong2 w0 = wA;
            wA = wB;
            if (kk + 2 < KQ) wB = wp[(kk + 2) * G4 + g0];
            const ulonglong2* zq = (const ulonglong2*)(zsm + kk * 4);
#pragma unroll
            for (int b = 0; b < BT; b++) {
                ulonglong2 zb = zq[b * (KPAD / 4)];   // warp-broadcast LDS.128
                a0[b] = ffma2(zb.x, w0.x, a0[b]);
                a0[b] = ffma2(zb.y, w0.y, a0[b]);
            }
        }

#pragma unroll
        for (int b = 0; b < BT; b++) gsm[b * G4 + g0] = upsum(a0[b]) + bs0;
        __syncthreads();   // gates visible

        // ---- elementwise: one warp per batch row, 4 j's per lane ----
        {
            const int b  = tid >> 5;            // warp id = batch row
            const int j0 = (tid & 31) * 4;
            const float* gb = gsm + b * G4;
            float* cb = csm + b * HID;
            float4 gi4 = *(const float4*)(gb + j0);
            float4 gf4 = *(const float4*)(gb + HID + j0);
            float4 gg4 = *(const float4*)(gb + 2 * HID + j0);
            float4 go4 = *(const float4*)(gb + 3 * HID + j0);
            float4 c4  = *(const float4*)(cb + j0);
            float hv[4];
            c4.x = sigm(gf4.x) * c4.x + sigm(gi4.x) * tanhx(gg4.x);
            c4.y = sigm(gf4.y) * c4.y + sigm(gi4.y) * tanhx(gg4.y);
            c4.z = sigm(gf4.z) * c4.z + sigm(gi4.z) * tanhx(gg4.z);
            c4.w = sigm(gf4.w) * c4.w + sigm(gi4.w) * tanhx(gg4.w);
            hv[0] = sigm(go4.x) * tanhx(c4.x);
            hv[1] = sigm(go4.y) * tanhx(c4.y);
            hv[2] = sigm(go4.z) * tanhx(c4.z);
            hv[3] = sigm(go4.w) * tanhx(c4.w);
            *(float4*)(cb + j0) = c4;
            *(float4*)(zsm + b * KPAD + XW + j0) = make_float4(hv[0], hv[1], hv[2], hv[3]);
            if (L0) {
                __nv_bfloat16 h0 = __float2bfloat16(hv[0]);
                __nv_bfloat16 h1 = __float2bfloat16(hv[1]);
                __nv_bfloat16 h2 = __float2bfloat16(hv[2]);
                __nv_bfloat16 h3 = __float2bfloat16(hv[3]);
                __nv_bfloat162 hb[2] = {{h0, h1}, {h2, h3}};
                __nv_bfloat162 lb[2] = {
                    {__float2bfloat16(hv[0] - __bfloat162float(h0)),
                     __float2bfloat16(hv[1] - __bfloat162float(h1))},
                    {__float2bfloat16(hv[2] - __bfloat162float(h2)),
                     __float2bfloat16(hv[3] - __bfloat162float(h3))}};
                size_t rowoff = ((size_t)tg * BATCH + b0 + b) * 256 + dir * HID + j0;
                *(uint2*)(g_ah + rowoff) = *(uint2*)hb;
                *(uint2*)(g_al + rowoff) = *(uint2*)lb;
            }
        }
        // loop-top __syncthreads orders h-writes before next gate GEMM
    }

    if (!L0) {
        __syncthreads();
        for (int i = tid; i < BT * HID; i += 512) {
            int b = i >> 7, j = i & 127;
            g_hstate[(dir * BATCH + b0 + b) * HID + j] = zsm[b * KPAD + XW + j];
            g_cstate[(dir * BATCH + b0 + b) * HID + j] = csm[b * HID + j];
        }
        if (seg == NSEG - 1) {
            for (int i = tid; i < BT * HID; i += 512) {
                int b = i >> 7, j = i & 127;
                g_final[(size_t)(b0 + b) * 256 + dir * HID + j] = zsm[b * KPAD + XW + j];
            }
        }
    }
}

// ---------------------------------------------------------------------------
// Classifier
// ---------------------------------------------------------------------------
__global__ void k_cls(const float* __restrict__ wc, const float* __restrict__ bc,
                      float* __restrict__ out) {
    int gw   = (blockIdx.x * blockDim.x + threadIdx.x) >> 5;
    int lane = threadIdx.x & 31;
    if (gw >= BATCH) return;
    const float* f = g_final + (size_t)gw * 256;
    float v[8];
#pragma unroll
    for (int i = 0; i < 8; i++) v[i] = f[lane + 32 * i];
#pragma unroll
    for (int nc = 0; nc < NCLS; nc++) {
        float s = 0.f;
#pragma unroll
        for (int i = 0; i < 8; i++) s += v[i] * wc[nc * 256 + lane + 32 * i];
#pragma unroll
        for (int off = 16; off; off >>= 1) s += __shfl_down_sync(0xffffffffu, s, off);
        if (lane == 0) out[gw * NCLS + nc] = s + bc[nc];
    }
}

// ---------------------------------------------------------------------------
extern "C" void kernel_launch(void* const* d_in, const int* in_sizes, int n_in,
                              void* d_out, int out_size) {
    (void)in_sizes; (void)n_in; (void)out_size;
    const float* x = (const float*)d_in[0];

    const int smem0 = (BT * KPAD0 + BT * G4 + BT * HID) * 4;           // 50176
    const int smem1 = (BT * KPAD1 + BT * G4 + BT * HID) * 4;           // 49152
    (void)cudaFuncSetAttribute(k_lstm<true>,  cudaFuncAttributeMaxDynamicSharedMemorySize, 65536);
    (void)cudaFuncSetAttribute(k_lstm<false>, cudaFuncAttributeMaxDynamicSharedMemorySize, 65536);
    (void)cudaFuncSetAttribute(k_xg1,         cudaFuncAttributeMaxDynamicSharedMemorySize, XSMEM);

    WPtrs W;
    for (int i = 0; i < 16; i++) W.p[i] = (const float*)d_in[1 + i];

    k_transpose<<<(TLEN * BATCH * 16 + 255) / 256, 256>>>(x);
    k_pack_whh<<<dim3((KPAD0 * G4 + 255) / 256, 4), 256>>>(W);
    k_pack_wb1<<<(2 * G4 * 256 + 255) / 256, 256>>>((const float*)d_in[9], (const float*)d_in[13]);

    k_lstm<true ><<<dim3(BATCH / BT, 2), 512, smem0>>>(0);
    for (int seg = 0; seg < NSEG; seg++) {
        k_xg1<<<dim3((SEGT * BATCH) / 128, 8), 256, XSMEM>>>(seg);
        k_lstm<false><<<dim3(BATCH / BT, 2), 512, smem1>>>(seg);
    }

    k_cls<<<BATCH / 8, 256>>>((const float*)d_in[17], (const float*)d_in[18], (float*)d_out);
}

// round 13
// speedup vs baseline: 1.1350x; 1.0227x over previous
#include <cuda_runtime.h>
#include <cuda_bf16.h>
#include <cstdint>

#define TLEN  512
#define BATCH 1024
#define HID   128
#define G4    512
#define NCLS  6
#define BT    16
#define KPAD0 144    // 16 (padded x, C=9) + 128 (h)
#define KPAD1 128    // h only (input projection precomputed)
#define SEGT  128    // timesteps per L1 segment
#define NSEG  (TLEN / SEGT)

// ---------------------------------------------------------------------------
// Scratch (device globals; total must stay well under 2 GB — host shadow .bss)
// ---------------------------------------------------------------------------
__device__ __align__(16) float g_xT[(size_t)TLEN * BATCH * 16];              // 32 MB
__device__ __align__(16) __nv_bfloat16 g_ah[(size_t)TLEN * BATCH * 256];     // 256 MB
__device__ __align__(16) __nv_bfloat16 g_al[(size_t)TLEN * BATCH * 256];     // 256 MB
__device__ __align__(16) float g_xg1f[(size_t)SEGT * BATCH * G4];            // 256 MB (fwd chunk)
__device__ __align__(16) float g_xg1r[(size_t)SEGT * BATCH * G4];            // 256 MB (rev chunk)
__device__ __align__(16) float g_hstate[2 * BATCH * HID];                    // 1 MB
__device__ __align__(16) float g_cstate[2 * BATCH * HID];                    // 1 MB
__device__ __align__(16) float g_final[(size_t)BATCH * 256];
__device__ __align__(16) float g_wp0[2 * KPAD0 * G4];
__device__ __align__(16) float g_wp1[2 * KPAD1 * G4];
__device__ __align__(16) __nv_bfloat16 g_wb1h[2 * 512 * 256];                // W_ih_l1 bf16 hi [dir][n][k]
__device__ __align__(16) __nv_bfloat16 g_wb1l[2 * 512 * 256];                // W_ih_l1 bf16 lo
__device__ float g_bias[4 * G4];

// Single dynamic-smem symbol (one type everywhere)
extern __shared__ char smem_raw[];

// ---------------------------------------------------------------------------
// Scalar helpers
// ---------------------------------------------------------------------------
__device__ __forceinline__ unsigned long long ffma2(unsigned long long a,
                                                    unsigned long long b,
                                                    unsigned long long c) {
    unsigned long long d;
    asm("fma.rn.f32x2 %0, %1, %2, %3;" : "=l"(d) : "l"(a), "l"(b), "l"(c));
    return d;
}
__device__ __forceinline__ float upsum(unsigned long long a) {
    float lo, hi;
    asm("mov.b64 {%0, %1}, %2;" : "=f"(lo), "=f"(hi) : "l"(a));
    return lo + hi;
}
__device__ __forceinline__ unsigned long long pack2(float lo, float hi) {
    unsigned long long r;
    asm("mov.b64 %0, {%1, %2};" : "=l"(r) : "f"(lo), "f"(hi));
    return r;
}
__device__ __forceinline__ float sigm(float x) {
    return __fdividef(1.f, 1.f + __expf(-x));
}
__device__ __forceinline__ float tanhx(float x) {
    return __fdividef(2.f, 1.f + __expf(-2.f * x)) - 1.f;
}
__device__ __forceinline__ uint32_t smem_u32(const void* p) {
    uint32_t a;
    asm("{ .reg .u64 t; cvta.to.shared.u64 t, %1; cvt.u32.u64 %0, t; }" : "=r"(a) : "l"(p));
    return a;
}
__device__ __forceinline__ void cp16(uint32_t saddr, const void* gptr) {
    asm volatile("cp.async.cg.shared.global [%0], [%1], 16;"
                 :: "r"(saddr), "l"(gptr) : "memory");
}

// mma.sync m16n8k16 bf16 -> fp32 accumulate (sm_80+, valid on family target)
__device__ __forceinline__ void mma16816(float* c,
                                         uint32_t a0, uint32_t a1, uint32_t a2, uint32_t a3,
                                         uint32_t b0, uint32_t b1) {
    asm volatile(
        "mma.sync.aligned.m16n8k16.row.col.f32.bf16.bf16.f32 "
        "{%0,%1,%2,%3}, {%4,%5,%6,%7}, {%8,%9}, {%0,%1,%2,%3};"
        : "+f"(c[0]), "+f"(c[1]), "+f"(c[2]), "+f"(c[3])
        : "r"(a0), "r"(a1), "r"(a2), "r"(a3), "r"(b0), "r"(b1));
}

// ---------------------------------------------------------------------------
// Prep: transpose x [B,9,T] -> g_xT [T,B,16] (cols 9..15 zero)
// ---------------------------------------------------------------------------
__global__ void k_transpose(const float* __restrict__ x) {
    size_t o = (size_t)blockIdx.x * blockDim.x + threadIdx.x;
    if (o >= (size_t)TLEN * BATCH * 16) return;
    int c = (int)(o & 15);
    size_t tb = o >> 4;
    int b = (int)(tb % BATCH);
    int t = (int)(tb / BATCH);
    g_xT[o] = (c < 9) ? x[((size_t)b * 9 + c) * TLEN + t] : 0.f;
}

// ---------------------------------------------------------------------------
// Pack scan weights, quad-interleaved wp[kk][g][4]; bias sums.
// which: 0=l0f 1=l0r (K=144), 2=l1f 3=l1r (K=128, h only)
// ---------------------------------------------------------------------------
struct WPtrs { const float* p[16]; };

__global__ void k_pack_whh(WPtrs W) {
    const int which = blockIdx.y;
    const float* wih = W.p[which * 4 + 0];
    const float* whh = W.p[which * 4 + 1];
    const float* bih = W.p[which * 4 + 2];
    const float* bhh = W.p[which * 4 + 3];
    const int kpad = (which < 2) ? KPAD0 : KPAD1;
    int o = blockIdx.x * blockDim.x + threadIdx.x;
    if (o < G4) g_bias[which * G4 + o] = bih[o] + bhh[o];
    if (o >= kpad * G4) return;
    int kk = o / (G4 * 4);
    int rem = o % (G4 * 4);
    int g = rem / 4, j = rem % 4;
    int k = kk * 4 + j;
    float v = 0.f;
    if (which < 2) {
        if (k < 9)                      v = wih[g * 9 + k];
        else if (k >= 16 && k < 144)    v = whh[g * HID + (k - 16)];
        g_wp0[which * KPAD0 * G4 + o] = v;
    } else {
        v = whh[g * HID + k];
        g_wp1[(which - 2) * KPAD1 * G4 + o] = v;
    }
}

// ---------------------------------------------------------------------------
// Pack W_ih_l1 fp32 -> bf16 hi/lo, plain [dir][512 n][256 k] row-major
// ---------------------------------------------------------------------------
__global__ void k_pack_wb1(const float* __restrict__ wf, const float* __restrict__ wr) {
    int o = blockIdx.x * blockDim.x + threadIdx.x;
    if (o >= 2 * G4 * 256) return;
    int dir = o / (G4 * 256);
    int rem = o % (G4 * 256);
    const float* w = dir ? wr : wf;
    float v = w[rem];
    __nv_bfloat16 h = __float2bfloat16(v);
    __nv_bfloat16 l = __float2bfloat16(v - __bfloat162float(h));
    g_wb1h[o] = h;
    g_wb1l[o] = l;
}

// ---------------------------------------------------------------------------
// xg1 chunk GEMM: xg = out0 @ W_ih_l1^T + bias over SEGT timesteps.
// Grid (8, 1024): x = dir*4 + ntile (FAST axis -> the 8 consumers of one
// A-tile are schedule-adjacent => A served from L2, DRAM traffic /4).
// Block 256 thr = 8 warps (2m x 4n), tile 128m x 128n x K256 in 32-chunks,
// cp.async double-buffered, occupancy 2. bf16 3-split (AhBh + AhBl + AlBh).
// ---------------------------------------------------------------------------
#define XSTR   40                      // smem row stride (bf16)
#define XMAT   (128 * XSTR)            // one matrix tile (bf16 elems)
#define XSTAGE (4 * XMAT)              // Ah, Al, Bh, Bl
#define XSMEM  (2 * XSTAGE * 2)        // bytes: 2 stages

__global__ void __launch_bounds__(256, 2) k_xg1(int seg) {
    __nv_bfloat16* sm = (__nv_bfloat16*)smem_raw;
    const uint32_t sbase = smem_u32(sm);

    const int tid  = threadIdx.x;
    const int wid  = tid >> 5, lane = tid & 31;
    const int g    = lane >> 2, tig = lane & 3;
    const int wm   = (wid & 1) * 64;
    const int wn   = (wid >> 1) * 32;
    const int dir  = blockIdx.x >> 2;
    const int n0   = (blockIdx.x & 3) * 128;
    const int t0   = dir ? (TLEN - (seg + 1) * SEGT) : (seg * SEGT);
    const size_t mg0 = (size_t)t0 * BATCH + (size_t)blockIdx.y * 128;   // global A row
    const size_t ml0 = (size_t)blockIdx.y * 128;                        // local out row

    const __nv_bfloat16* gBh = g_wb1h + ((size_t)dir * 512 + n0) * 256;
    const __nv_bfloat16* gBl = g_wb1l + ((size_t)dir * 512 + n0) * 256;

    // stage loader: 4 matrices x 128 rows x 32 k (4 x 16B per row) = 2048 cp16
    auto load_stage = [&](int kc, int stage) {
        const uint32_t sb = sbase + (uint32_t)stage * XSTAGE * 2;
#pragma unroll
        for (int j = 0; j < 8; j++) {
            int i = tid + 256 * j;
            int mat = i >> 9;
            int r   = (i >> 2) & 127;
            int c   = i & 3;
            const __nv_bfloat16* gp;
            if (mat == 0)      gp = g_ah + (mg0 + r) * 256 + kc * 32 + c * 8;
            else if (mat == 1) gp = g_al + (mg0 + r) * 256 + kc * 32 + c * 8;
            else if (mat == 2) gp = gBh + (size_t)r * 256 + kc * 32 + c * 8;
            else               gp = gBl + (size_t)r * 256 + kc * 32 + c * 8;
            uint32_t sa = sb + (uint32_t)(mat * XMAT + r * XSTR + c * 8) * 2;
            cp16(sa, gp);
        }
        asm volatile("cp.async.commit_group;" ::: "memory");
    };

    float acc[4][4][4];
#pragma unroll
    for (int mf = 0; mf < 4; mf++)
#pragma unroll
        for (int nf = 0; nf < 4; nf++)
#pragma unroll
            for (int q = 0; q < 4; q++) acc[mf][nf][q] = 0.f;

    load_stage(0, 0);

    for (int kc = 0; kc < 8; kc++) {
        if (kc + 1 < 8) {
            load_stage(kc + 1, (kc + 1) & 1);
            asm volatile("cp.async.wait_group 1;" ::: "memory");
        } else {
            asm volatile("cp.async.wait_group 0;" ::: "memory");
        }
        __syncthreads();   // stage kc visible to all warps

        const __nv_bfloat16* sAh = sm + (kc & 1) * XSTAGE;
        const __nv_bfloat16* sAl = sAh + XMAT;
        const __nv_bfloat16* sBh = sAh + 2 * XMAT;
        const __nv_bfloat16* sBl = sAh + 3 * XMAT;

#pragma unroll
        for (int s = 0; s < 2; s++) {
            const int kb = s * 16 + 2 * tig;
            uint32_t bh[4][2], bl[4][2];
#pragma unroll
            for (int nf = 0; nf < 4; nf++) {
                const int n = wn + nf * 8 + g;
                bh[nf][0] = *(const uint32_t*)(sBh + n * XSTR + kb);
                bh[nf][1] = *(const uint32_t*)(sBh + n * XSTR + kb + 8);
                bl[nf][0] = *(const uint32_t*)(sBl + n * XSTR + kb);
                bl[nf][1] = *(const uint32_t*)(sBl + n * XSTR + kb + 8);
            }
#pragma unroll
            for (int mf = 0; mf < 4; mf++) {
                const int mr = wm + mf * 16 + g;
                uint32_t ah0 = *(const uint32_t*)(sAh + mr * XSTR + kb);
                uint32_t ah1 = *(const uint32_t*)(sAh + (mr + 8) * XSTR + kb);
                uint32_t ah2 = *(const uint32_t*)(sAh + mr * XSTR + kb + 8);
                uint32_t ah3 = *(const uint32_t*)(sAh + (mr + 8) * XSTR + kb + 8);
                uint32_t al0 = *(const uint32_t*)(sAl + mr * XSTR + kb);
                uint32_t al1 = *(const uint32_t*)(sAl + (mr + 8) * XSTR + kb);
                uint32_t al2 = *(const uint32_t*)(sAl + mr * XSTR + kb + 8);
                uint32_t al3 = *(const uint32_t*)(sAl + (mr + 8) * XSTR + kb + 8);
#pragma unroll
                for (int nf = 0; nf < 4; nf++) {
                    mma16816(acc[mf][nf], ah0, ah1, ah2, ah3, bh[nf][0], bh[nf][1]);
                    mma16816(acc[mf][nf], ah0, ah1, ah2, ah3, bl[nf][0], bl[nf][1]);
                    mma16816(acc[mf][nf], al0, al1, al2, al3, bh[nf][0], bh[nf][1]);
                }
            }
        }
        __syncthreads();   // all warps done with stage kc before it is reloaded
    }

    // ---- epilogue: +bias, write fp32 xg chunk ----
    float* out = dir ? g_xg1r : g_xg1f;
    const float* bias = g_bias + (2 + dir) * G4 + n0;
#pragma unroll
    for (int mf = 0; mf < 4; mf++) {
#pragma unroll
        for (int nf = 0; nf < 4; nf++) {
            const int col = wn + nf * 8 + 2 * tig;
            const size_t row = ml0 + wm + mf * 16 + g;
            float2 bv = *(const float2*)(bias + col);
            float2 v0 = make_float2(acc[mf][nf][0] + bv.x, acc[mf][nf][1] + bv.y);
            float2 v1 = make_float2(acc[mf][nf][2] + bv.x, acc[mf][nf][3] + bv.y);
            *(float2*)(out + row * G4 + n0 + col)       = v0;
            *(float2*)(out + (row + 8) * G4 + n0 + col) = v1;
        }
    }
}

// ---------------------------------------------------------------------------
// BiLSTM direction-layer scan. 512 threads, 1 gate/thread, 16 warps/SM.
// Weight prefetch distance 3 (use-distance > L2 far-die latency).
// L0: full T, K=144 (x fused), writes bf16 hi/lo out0.
// L1: one SEGT segment, K=128, xg-chunk init, h/c carried via g_*state.
// ---------------------------------------------------------------------------
template <bool L0>
__global__ void __launch_bounds__(512, 1) k_lstm(int seg) {
    constexpr int KPAD = L0 ? KPAD0 : KPAD1;
    constexpr int XW   = L0 ? 16 : 0;
    constexpr int KQ   = KPAD / 4;
    constexpr int NT   = L0 ? TLEN : SEGT;

    float* smem = (float*)smem_raw;
    float* zsm = smem;                    // [BT][KPAD]  z = [x | h]
    float* gsm = smem + BT * KPAD;        // [BT][G4]
    float* csm = gsm + BT * G4;           // [BT][HID]

    const int tid = threadIdx.x;
    const int dir = blockIdx.y;
    const int b0  = blockIdx.x * BT;
    const int g0  = tid;                  // one gate per thread

    const float* wpraw = L0 ? (g_wp0 + dir * KPAD0 * G4) : (g_wp1 + dir * KPAD1 * G4);
    const ulonglong2* __restrict__ wp = (const ulonglong2*)wpraw;
    const float bs0 = L0 ? g_bias[dir * G4 + g0] : 0.f;
    const float* __restrict__ xgb = L0 ? nullptr : (dir ? g_xg1r : g_xg1f);
    const int tbase = L0 ? 0 : (dir ? (TLEN - (seg + 1) * SEGT) : (seg * SEGT));

    if (L0 || seg == 0) {
        for (int i = tid; i < BT * KPAD; i += 512) zsm[i] = 0.f;
        for (int i = tid; i < BT * HID;  i += 512) csm[i] = 0.f;
    } else {
        for (int i = tid; i < BT * HID; i += 512) {
            int b = i >> 7, j = i & 127;
            zsm[b * KPAD + XW + j] = g_hstate[(dir * BATCH + b0 + b) * HID + j];
            csm[b * HID + j]       = g_cstate[(dir * BATCH + b0 + b) * HID + j];
        }
    }
    __syncthreads();

    for (int t = 0; t < NT; ++t) {
        // global time index for this step
        const int tg = dir ? (TLEN - 1 - (L0 ? t : (seg * SEGT + t))) : (tbase + t);

        float xa0[BT];
        if (!L0) {
            const int tl = tg - tbase;   // local index in xg chunk, [0, SEGT)
            const float* xg = xgb + ((size_t)tl * BATCH + b0) * G4;
#pragma unroll
            for (int b = 0; b < BT; b++) xa0[b] = xg[b * G4 + g0];
        } else {
            const float4* src = (const float4*)(g_xT + ((size_t)tg * BATCH + b0) * 16);
            for (int i = tid; i < BT * 4; i += 512) {
                int b = i >> 2, c = i & 3;
                *(float4*)&zsm[b * KPAD + c * 4] = src[b * 4 + c];
            }
        }
        __syncthreads();   // x/h ready

        unsigned long long a0[BT];
#pragma unroll
        for (int b = 0; b < BT; b++) a0[b] = L0 ? 0ull : pack2(xa0[b], 0.f);

        // weight stream: prefetch distance 3 (> L2 far-die latency)
        ulonglong2 wv0 = wp[g0];
        ulonglong2 wv1 = wp[G4 + g0];
        ulonglong2 wv2 = wp[2 * G4 + g0];
        for (int kk = 0; kk < KQ; kk++) {
            ulonglong2 w0 = wv0;
            wv0 = wv1; wv1 = wv2;
            if (kk + 3 < KQ) wv2 = wp[(kk + 3) * G4 + g0];
            const ulonglong2* zq = (const ulonglong2*)(zsm + kk * 4);
#pragma unroll
            for (int b = 0; b < BT; b++) {
                ulonglong2 zb = zq[b * (KPAD / 4)];   // warp-broadcast LDS.128
                a0[b] = ffma2(zb.x, w0.x, a0[b]);
                a0[b] = ffma2(zb.y, w0.y, a0[b]);
            }
        }

#pragma unroll
        for (int b = 0; b < BT; b++) gsm[b * G4 + g0] = upsum(a0[b]) + bs0;
        __syncthreads();   // gates visible

        // ---- elementwise: one warp per batch row, 4 j's per lane ----
        {
            const int b  = tid >> 5;            // warp id = batch row
            const int j0 = (tid & 31) * 4;
            const float* gb = gsm + b * G4;
            float* cb = csm + b * HID;
            float4 gi4 = *(const float4*)(gb + j0);
            float4 gf4 = *(const float4*)(gb + HID + j0);
            float4 gg4 = *(const float4*)(gb + 2 * HID + j0);
            float4 go4 = *(const float4*)(gb + 3 * HID + j0);
            float4 c4  = *(const float4*)(cb + j0);
            float hv[4];
            c4.x = sigm(gf4.x) * c4.x + sigm(gi4.x) * tanhx(gg4.x);
            c4.y = sigm(gf4.y) * c4.y + sigm(gi4.y) * tanhx(gg4.y);
            c4.z = sigm(gf4.z) * c4.z + sigm(gi4.z) * tanhx(gg4.z);
            c4.w = sigm(gf4.w) * c4.w + sigm(gi4.w) * tanhx(gg4.w);
            hv[0] = sigm(go4.x) * tanhx(c4.x);
            hv[1] = sigm(go4.y) * tanhx(c4.y);
            hv[2] = sigm(go4.z) * tanhx(c4.z);
            hv[3] = sigm(go4.w) * tanhx(c4.w);
            *(float4*)(cb + j0) = c4;
            *(float4*)(zsm + b * KPAD + XW + j0) = make_float4(hv[0], hv[1], hv[2], hv[3]);
            if (L0) {
                __nv_bfloat16 h0 = __float2bfloat16(hv[0]);
                __nv_bfloat16 h1 = __float2bfloat16(hv[1]);
                __nv_bfloat16 h2 = __float2bfloat16(hv[2]);
                __nv_bfloat16 h3 = __float2bfloat16(hv[3]);
                __nv_bfloat162 hb[2] = {{h0, h1}, {h2, h3}};
                __nv_bfloat162 lb[2] = {
                    {__float2bfloat16(hv[0] - __bfloat162float(h0)),
                     __float2bfloat16(hv[1] - __bfloat162float(h1))},
                    {__float2bfloat16(hv[2] - __bfloat162float(h2)),
                     __float2bfloat16(hv[3] - __bfloat162float(h3))}};
                size_t rowoff = ((size_t)tg * BATCH + b0 + b) * 256 + dir * HID + j0;
                *(uint2*)(g_ah + rowoff) = *(uint2*)hb;
                *(uint2*)(g_al + rowoff) = *(uint2*)lb;
            }
        }
        // loop-top __syncthreads orders h-writes before next gate GEMM
    }

    if (!L0) {
        __syncthreads();
        for (int i = tid; i < BT * HID; i += 512) {
            int b = i >> 7, j = i & 127;
            g_hstate[(dir * BATCH + b0 + b) * HID + j] = zsm[b * KPAD + XW + j];
            g_cstate[(dir * BATCH + b0 + b) * HID + j] = csm[b * HID + j];
        }
        if (seg == NSEG - 1) {
            for (int i = tid; i < BT * HID; i += 512) {
                int b = i >> 7, j = i & 127;
                g_final[(size_t)(b0 + b) * 256 + dir * HID + j] = zsm[b * KPAD + XW + j];
            }
        }
    }
}

// ---------------------------------------------------------------------------
// Classifier
// ---------------------------------------------------------------------------
__global__ void k_cls(const float* __restrict__ wc, const float* __restrict__ bc,
                      float* __restrict__ out) {
    int gw   = (blockIdx.x * blockDim.x + threadIdx.x) >> 5;
    int lane = threadIdx.x & 31;
    if (gw >= BATCH) return;
    const float* f = g_final + (size_t)gw * 256;
    float v[8];
#pragma unroll
    for (int i = 0; i < 8; i++) v[i] = f[lane + 32 * i];
#pragma unroll
    for (int nc = 0; nc < NCLS; nc++) {
        float s = 0.f;
#pragma unroll
        for (int i = 0; i < 8; i++) s += v[i] * wc[nc * 256 + lane + 32 * i];
#pragma unroll
        for (int off = 16; off; off >>= 1) s += __shfl_down_sync(0xffffffffu, s, off);
        if (lane == 0) out[gw * NCLS + nc] = s + bc[nc];
    }
}

// ---------------------------------------------------------------------------
extern "C" void kernel_launch(void* const* d_in, const int* in_sizes, int n_in,
                              void* d_out, int out_size) {
    (void)in_sizes; (void)n_in; (void)out_size;
    const float* x = (const float*)d_in[0];

    const int smem0 = (BT * KPAD0 + BT * G4 + BT * HID) * 4;           // 50176
    const int smem1 = (BT * KPAD1 + BT * G4 + BT * HID) * 4;           // 49152
    (void)cudaFuncSetAttribute(k_lstm<true>,  cudaFuncAttributeMaxDynamicSharedMemorySize, 65536);
    (void)cudaFuncSetAttribute(k_lstm<false>, cudaFuncAttributeMaxDynamicSharedMemorySize, 65536);
    (void)cudaFuncSetAttribute(k_xg1,         cudaFuncAttributeMaxDynamicSharedMemorySize, XSMEM);

    WPtrs W;
    for (int i = 0; i < 16; i++) W.p[i] = (const float*)d_in[1 + i];

    k_transpose<<<(TLEN * BATCH * 16 + 255) / 256, 256>>>(x);
    k_pack_whh<<<dim3((KPAD0 * G4 + 255) / 256, 4), 256>>>(W);
    k_pack_wb1<<<(2 * G4 * 256 + 255) / 256, 256>>>((const float*)d_in[9], (const float*)d_in[13]);

    k_lstm<true ><<<dim3(BATCH / BT, 2), 512, smem0>>>(0);
    for (int seg = 0; seg < NSEG; seg++) {
        k_xg1<<<dim3(8, (SEGT * BATCH) / 128), 256, XSMEM>>>(seg);
        k_lstm<false><<<dim3(BATCH / BT, 2), 512, smem1>>>(seg);
    }

    k_cls<<<BATCH / 8, 256>>>((const float*)d_in[17], (const float*)d_in[18], (float*)d_out);
}

// round 14
// speedup vs baseline: 1.8821x; 1.6583x over previous
#include <cuda_runtime.h>
#include <cuda_bf16.h>
#include <cstdint>

#define TLEN  512
#define BATCH 1024
#define HID   128
#define G4    512
#define NCLS  6
#define BT    16
#define SEGT  128    // timesteps per segment (both layers segmented)
#define NSEG  (TLEN / SEGT)
#define HSTR  136    // h smem row stride (bf16), conflict-free
#define GST   520    // gate smem row stride (float)

// ---------------------------------------------------------------------------
// Scratch (device globals; total well under 2 GB)
// ---------------------------------------------------------------------------
__device__ __align__(16) float g_xT[(size_t)TLEN * BATCH * 16];              // 32 MB
__device__ __align__(16) __nv_bfloat16 g_ah[(size_t)TLEN * BATCH * 256];     // 256 MB
__device__ __align__(16) __nv_bfloat16 g_al[(size_t)TLEN * BATCH * 256];     // 256 MB
__device__ __align__(16) float g_xg1f[(size_t)SEGT * BATCH * G4];            // 256 MB (chunk, reused L0+L1)
__device__ __align__(16) float g_xg1r[(size_t)SEGT * BATCH * G4];            // 256 MB
__device__ __align__(16) float g_hstate[2 * BATCH * HID];
__device__ __align__(16) float g_cstate[2 * BATCH * HID];
__device__ __align__(16) float g_final[(size_t)BATCH * 256];
__device__ __align__(16) uint32_t g_wfh[4 * 32768];                          // W_hh bf16-hi fragments
__device__ __align__(16) uint32_t g_wfl[4 * 32768];                          // W_hh bf16-lo fragments
__device__ __align__(16) __nv_bfloat16 g_wb1h[2 * 512 * 256];                // W_ih_l1 bf16 hi
__device__ __align__(16) __nv_bfloat16 g_wb1l[2 * 512 * 256];                // W_ih_l1 bf16 lo
__device__ float g_bias[4 * G4];

extern __shared__ char smem_raw[];

// ---------------------------------------------------------------------------
// Helpers
// ---------------------------------------------------------------------------
__device__ __forceinline__ float sigm(float x) {
    return __fdividef(1.f, 1.f + __expf(-x));
}
__device__ __forceinline__ float tanhx(float x) {
    return __fdividef(2.f, 1.f + __expf(-2.f * x)) - 1.f;
}
__device__ __forceinline__ uint32_t smem_u32(const void* p) {
    uint32_t a;
    asm("{ .reg .u64 t; cvta.to.shared.u64 t, %1; cvt.u32.u64 %0, t; }" : "=r"(a) : "l"(p));
    return a;
}
__device__ __forceinline__ void cp16(uint32_t saddr, const void* gptr) {
    asm volatile("cp.async.cg.shared.global [%0], [%1], 16;"
                 :: "r"(saddr), "l"(gptr) : "memory");
}
__device__ __forceinline__ uint32_t packbf2(float a, float b) {
    __nv_bfloat162 p = {__float2bfloat16(a), __float2bfloat16(b)};
    return *(uint32_t*)&p;
}
__device__ __forceinline__ void mma16816(float* c,
                                         uint32_t a0, uint32_t a1, uint32_t a2, uint32_t a3,
                                         uint32_t b0, uint32_t b1) {
    asm volatile(
        "mma.sync.aligned.m16n8k16.row.col.f32.bf16.bf16.f32 "
        "{%0,%1,%2,%3}, {%4,%5,%6,%7}, {%8,%9}, {%0,%1,%2,%3};"
        : "+f"(c[0]), "+f"(c[1]), "+f"(c[2]), "+f"(c[3])
        : "r"(a0), "r"(a1), "r"(a2), "r"(a3), "r"(b0), "r"(b1));
}

struct WPtrs { const float* p[16]; };

// ---------------------------------------------------------------------------
// Prep: transpose x [B,9,T] -> g_xT [T,B,16] (cols 9..15 zero)
// ---------------------------------------------------------------------------
__global__ void k_transpose(const float* __restrict__ x) {
    size_t o = (size_t)blockIdx.x * blockDim.x + threadIdx.x;
    if (o >= (size_t)TLEN * BATCH * 16) return;
    int c = (int)(o & 15);
    size_t tb = o >> 4;
    int b = (int)(tb % BATCH);
    int t = (int)(tb / BATCH);
    g_xT[o] = (c < 9) ? x[((size_t)b * 9 + c) * TLEN + t] : 0.f;
}

// ---------------------------------------------------------------------------
// Bias sums: g_bias[which*512+n] = b_ih + b_hh.  which: 0=l0f 1=l0r 2=l1f 3=l1r
// ---------------------------------------------------------------------------
__global__ void k_pack_bias(WPtrs W) {
    int o = blockIdx.x * 256 + threadIdx.x;
    if (o >= 4 * G4) return;
    int which = o >> 9, n = o & 511;
    g_bias[o] = W.p[which * 4 + 2][n] + W.p[which * 4 + 3][n];
}

// ---------------------------------------------------------------------------
// Pack W_hh (all 4 layer-dirs) into m16n8k16 B-fragment order, bf16 hi/lo:
// idx within which = ((kf*4+nf)*2+r)*512 + w*32+lane;
// element: n = w*32+nf*8+lane/4, k = kf*16 + r*8 + 2*(lane%4), pair (k,k+1).
// ---------------------------------------------------------------------------
__global__ void k_pack_wfrag(WPtrs W) {
    int o = blockIdx.x * 256 + threadIdx.x;
    if (o >= 4 * 32768) return;
    int which = o >> 15;
    int rem = o & 32767;
    int pos = rem & 511;
    int rr  = rem >> 9;
    int r = rr & 1, nf = (rr >> 1) & 3, kf = rr >> 3;
    int lane = pos & 31;
    int n = (pos >> 5) * 32 + nf * 8 + (lane >> 2);
    int k = kf * 16 + r * 8 + 2 * (lane & 3);
    const float* whh = W.p[which * 4 + 1];
    float w0 = whh[n * HID + k], w1 = whh[n * HID + k + 1];
    __nv_bfloat16 h0 = __float2bfloat16(w0), h1 = __float2bfloat16(w1);
    float l0 = w0 - __bfloat162float(h0), l1 = w1 - __bfloat162float(h1);
    g_wfh[o] = packbf2(__bfloat162float(h0), __bfloat162float(h1));
    g_wfl[o] = packbf2(l0, l1);
}

// ---------------------------------------------------------------------------
// Pack W_ih_l1 fp32 -> bf16 hi/lo (for k_xg1)
// ---------------------------------------------------------------------------
__global__ void k_pack_wb1(const float* __restrict__ wf, const float* __restrict__ wr) {
    int o = blockIdx.x * blockDim.x + threadIdx.x;
    if (o >= 2 * G4 * 256) return;
    int dir = o / (G4 * 256);
    int rem = o % (G4 * 256);
    const float* w = dir ? wr : wf;
    float v = w[rem];
    __nv_bfloat16 h = __float2bfloat16(v);
    g_wb1h[o] = h;
    g_wb1l[o] = __float2bfloat16(v - __bfloat162float(h));
}

// ---------------------------------------------------------------------------
// xg0 chunk: L0 input projection (K=9, fp32) + bias into xg buffers.
// Grid (SEGT*BATCH/32, 2). Block 256: 8 warps x 4 rows each; coalesced stores.
// ---------------------------------------------------------------------------
__global__ void __launch_bounds__(256, 4) k_xg0(WPtrs W, int seg) {
    float* sW = (float*)smem_raw;          // [512*9]
    float* sb = sW + 512 * 9;              // [512]
    const int tid = threadIdx.x, wid = tid >> 5, lane = tid & 31;
    const int dir = blockIdx.y;
    const float* wih = W.p[dir * 4 + 0];
    for (int i = tid; i < 512 * 9; i += 256) sW[i] = wih[i];
    for (int i = tid; i < 512; i += 256) sb[i] = g_bias[dir * 512 + i];
    __syncthreads();
    const int t0 = dir ? (TLEN - (seg + 1) * SEGT) : (seg * SEGT);
    float* out = dir ? g_xg1r : g_xg1f;
    const float* xbase = g_xT + (size_t)t0 * BATCH * 16;
    const size_t rbase = (size_t)blockIdx.x * 32 + wid * 4;
    for (int rr = 0; rr < 4; rr++) {
        size_t row = rbase + rr;
        const float* xr = xbase + row * 16;
        float xv[9];
#pragma unroll
        for (int k = 0; k < 9; k++) xv[k] = xr[k];
#pragma unroll
        for (int cblk = 0; cblk < 4; cblk++) {
            int gbase = cblk * 128 + lane * 4;
            float4 o4;
            float* po = &o4.x;
#pragma unroll
            for (int u = 0; u < 4; u++) {
                int G = gbase + u;
                float s = sb[G];
#pragma unroll
                for (int k = 0; k < 9; k++) s += xv[k] * sW[G * 9 + k];
                po[u] = s;
            }
            *(float4*)(out + row * 512 + gbase) = o4;
        }
    }
}

// ---------------------------------------------------------------------------
// xg1 chunk GEMM (unchanged, validated): xg = out0 @ W_ih_l1^T + bias.
// ---------------------------------------------------------------------------
#define XSTR   40
#define XMAT   (128 * XSTR)
#define XSTAGE (4 * XMAT)
#define XSMEM  (2 * XSTAGE * 2)

__global__ void __launch_bounds__(256, 2) k_xg1(int seg) {
    __nv_bfloat16* sm = (__nv_bfloat16*)smem_raw;
    const uint32_t sbase = smem_u32(sm);

    const int tid  = threadIdx.x;
    const int wid  = tid >> 5, lane = tid & 31;
    const int g    = lane >> 2, tig = lane & 3;
    const int wm   = (wid & 1) * 64;
    const int wn   = (wid >> 1) * 32;
    const int dir  = blockIdx.x >> 2;
    const int n0   = (blockIdx.x & 3) * 128;
    const int t0   = dir ? (TLEN - (seg + 1) * SEGT) : (seg * SEGT);
    const size_t mg0 = (size_t)t0 * BATCH + (size_t)blockIdx.y * 128;
    const size_t ml0 = (size_t)blockIdx.y * 128;

    const __nv_bfloat16* gBh = g_wb1h + ((size_t)dir * 512 + n0) * 256;
    const __nv_bfloat16* gBl = g_wb1l + ((size_t)dir * 512 + n0) * 256;

    auto load_stage = [&](int kc, int stage) {
        const uint32_t sb = sbase + (uint32_t)stage * XSTAGE * 2;
#pragma unroll
        for (int j = 0; j < 8; j++) {
            int i = tid + 256 * j;
            int mat = i >> 9;
            int r   = (i >> 2) & 127;
            int c   = i & 3;
            const __nv_bfloat16* gp;
            if (mat == 0)      gp = g_ah + (mg0 + r) * 256 + kc * 32 + c * 8;
            else if (mat == 1) gp = g_al + (mg0 + r) * 256 + kc * 32 + c * 8;
            else if (mat == 2) gp = gBh + (size_t)r * 256 + kc * 32 + c * 8;
            else               gp = gBl + (size_t)r * 256 + kc * 32 + c * 8;
            uint32_t sa = sb + (uint32_t)(mat * XMAT + r * XSTR + c * 8) * 2;
            cp16(sa, gp);
        }
        asm volatile("cp.async.commit_group;" ::: "memory");
    };

    float acc[4][4][4];
#pragma unroll
    for (int mf = 0; mf < 4; mf++)
#pragma unroll
        for (int nf = 0; nf < 4; nf++)
#pragma unroll
            for (int q = 0; q < 4; q++) acc[mf][nf][q] = 0.f;

    load_stage(0, 0);

    for (int kc = 0; kc < 8; kc++) {
        if (kc + 1 < 8) {
            load_stage(kc + 1, (kc + 1) & 1);
            asm volatile("cp.async.wait_group 1;" ::: "memory");
        } else {
            asm volatile("cp.async.wait_group 0;" ::: "memory");
        }
        __syncthreads();

        const __nv_bfloat16* sAh = sm + (kc & 1) * XSTAGE;
        const __nv_bfloat16* sAl = sAh + XMAT;
        const __nv_bfloat16* sBh = sAh + 2 * XMAT;
        const __nv_bfloat16* sBl = sAh + 3 * XMAT;

#pragma unroll
        for (int s = 0; s < 2; s++) {
            const int kb = s * 16 + 2 * tig;
            uint32_t bh[4][2], bl[4][2];
#pragma unroll
            for (int nf = 0; nf < 4; nf++) {
                const int n = wn + nf * 8 + g;
                bh[nf][0] = *(const uint32_t*)(sBh + n * XSTR + kb);
                bh[nf][1] = *(const uint32_t*)(sBh + n * XSTR + kb + 8);
                bl[nf][0] = *(const uint32_t*)(sBl + n * XSTR + kb);
                bl[nf][1] = *(const uint32_t*)(sBl + n * XSTR + kb + 8);
            }
#pragma unroll
            for (int mf = 0; mf < 4; mf++) {
                const int mr = wm + mf * 16 + g;
                uint32_t ah0 = *(const uint32_t*)(sAh + mr * XSTR + kb);
                uint32_t ah1 = *(const uint32_t*)(sAh + (mr + 8) * XSTR + kb);
                uint32_t ah2 = *(const uint32_t*)(sAh + mr * XSTR + kb + 8);
                uint32_t ah3 = *(const uint32_t*)(sAh + (mr + 8) * XSTR + kb + 8);
                uint32_t al0 = *(const uint32_t*)(sAl + mr * XSTR + kb);
                uint32_t al1 = *(const uint32_t*)(sAl + (mr + 8) * XSTR + kb);
                uint32_t al2 = *(const uint32_t*)(sAl + mr * XSTR + kb + 8);
                uint32_t al3 = *(const uint32_t*)(sAl + (mr + 8) * XSTR + kb + 8);
#pragma unroll
                for (int nf = 0; nf < 4; nf++) {
                    mma16816(acc[mf][nf], ah0, ah1, ah2, ah3, bh[nf][0], bh[nf][1]);
                    mma16816(acc[mf][nf], ah0, ah1, ah2, ah3, bl[nf][0], bl[nf][1]);
                    mma16816(acc[mf][nf], al0, al1, al2, al3, bh[nf][0], bh[nf][1]);
                }
            }
        }
        __syncthreads();
    }

    float* out = dir ? g_xg1r : g_xg1f;
    const float* bias = g_bias + (2 + dir) * G4 + n0;
#pragma unroll
    for (int mf = 0; mf < 4; mf++) {
#pragma unroll
        for (int nf = 0; nf < 4; nf++) {
            const int col = wn + nf * 8 + 2 * tig;
            const size_t row = ml0 + wm + mf * 16 + g;
            float2 bv = *(const float2*)(bias + col);
            float2 v0 = make_float2(acc[mf][nf][0] + bv.x, acc[mf][nf][1] + bv.y);
            float2 v1 = make_float2(acc[mf][nf][2] + bv.x, acc[mf][nf][3] + bv.y);
            *(float2*)(out + row * G4 + n0 + col)       = v0;
            *(float2*)(out + (row + 8) * G4 + n0 + col) = v1;
        }
    }
}

// ---------------------------------------------------------------------------
// BiLSTM scan, mma.sync recurrence. 512 thr = 16 warps; warp w owns gates
// [w*32, w*32+32) (mma) and batch row w (elementwise).  Wh in registers,
// Wl in smem, h as bf16 hi/lo in smem.  Gates init from precomputed xg.
// L0 additionally writes h hi/lo to g_ah/g_al; L1 writes final hidden.
// smem: sWl 128K | gsm 16x520 f32 | hh,hl 16x136 bf16 | csm 16x128 f32
// ---------------------------------------------------------------------------
#define SC_SMEM (131072 + 33280 + 4352 + 4352 + 8192)   // 181248

template <bool L0>
__global__ void __launch_bounds__(512, 1) k_lstm(int seg) {
    uint32_t* sWl = (uint32_t*)smem_raw;
    float* gsm = (float*)(smem_raw + 131072);
    __nv_bfloat16* hh = (__nv_bfloat16*)(smem_raw + 131072 + 33280);
    __nv_bfloat16* hl = hh + 16 * HSTR;
    float* csm = (float*)(smem_raw + 131072 + 33280 + 2 * 4352);

    const int tid = threadIdx.x;
    const int w = tid >> 5, lane = tid & 31;
    const int g = lane >> 2, tig = lane & 3;
    const int dir = blockIdx.y;
    const int b0 = blockIdx.x * BT;
    const int n0 = w * 32;
    const int which = (L0 ? 0 : 2) + dir;
    const uint32_t* wfh = g_wfh + (size_t)which * 32768;
    const uint32_t* wfl = g_wfl + (size_t)which * 32768;
    const float* __restrict__ xgb = dir ? g_xg1r : g_xg1f;
    const int tbase = dir ? (TLEN - (seg + 1) * SEGT) : (seg * SEGT);

    // Wh -> registers (once)
    uint32_t wh[8][4][2];
#pragma unroll
    for (int kf = 0; kf < 8; kf++)
#pragma unroll
        for (int nf = 0; nf < 4; nf++)
#pragma unroll
            for (int r = 0; r < 2; r++)
                wh[kf][nf][r] = wfh[((kf * 4 + nf) * 2 + r) * 512 + tid];
    // Wl -> smem (once)
    for (int i = tid; i < 8192; i += 512)
        ((uint4*)sWl)[i] = ((const uint4*)wfl)[i];

    // state init
    if (seg == 0) {
        for (int i = tid; i < 16 * HSTR; i += 512) { hh[i] = __float2bfloat16(0.f); hl[i] = __float2bfloat16(0.f); }
        for (int i = tid; i < 16 * HID; i += 512) csm[i] = 0.f;
    } else {
        for (int i = tid; i < 16 * HID; i += 512) {
            int b = i >> 7, j = i & 127;
            float h = g_hstate[(dir * BATCH + b0 + b) * HID + j];
            __nv_bfloat16 h0 = __float2bfloat16(h);
            hh[b * HSTR + j] = h0;
            hl[b * HSTR + j] = __float2bfloat16(h - __bfloat162float(h0));
            csm[b * HID + j] = g_cstate[(dir * BATCH + b0 + b) * HID + j];
        }
        for (int i = tid; i < 16 * (HSTR - HID); i += 512) {   // zero pad cols
            int b = i / (HSTR - HID), j = HID + i % (HSTR - HID);
            hh[b * HSTR + j] = __float2bfloat16(0.f);
            hl[b * HSTR + j] = __float2bfloat16(0.f);
        }
    }
    __syncthreads();

    for (int t = 0; t < SEGT; ++t) {
        const int tl = dir ? (SEGT - 1 - t) : t;
        const int tg = tbase + tl;

        // acc init from xg (bias included)
        float acc[4][4];
        const float* xgr0 = xgb + ((size_t)tl * BATCH + b0 + g) * G4 + n0;
        const float* xgr1 = xgr0 + 8 * G4;
#pragma unroll
        for (int nf = 0; nf < 4; nf++) {
            float2 p0 = *(const float2*)(xgr0 + nf * 8 + 2 * tig);
            float2 p1 = *(const float2*)(xgr1 + nf * 8 + 2 * tig);
            acc[nf][0] = p0.x; acc[nf][1] = p0.y; acc[nf][2] = p1.x; acc[nf][3] = p1.y;
        }

        // gates += h @ Whh^T (3-split bf16 mma)
#pragma unroll
        for (int kf = 0; kf < 8; kf++) {
            const int kb = kf * 16 + 2 * tig;
            uint32_t ah0 = *(const uint32_t*)(hh + g * HSTR + kb);
            uint32_t ah1 = *(const uint32_t*)(hh + (g + 8) * HSTR + kb);
            uint32_t ah2 = *(const uint32_t*)(hh + g * HSTR + kb + 8);
            uint32_t ah3 = *(const uint32_t*)(hh + (g + 8) * HSTR + kb + 8);
            uint32_t al0 = *(const uint32_t*)(hl + g * HSTR + kb);
            uint32_t al1 = *(const uint32_t*)(hl + (g + 8) * HSTR + kb);
            uint32_t al2 = *(const uint32_t*)(hl + g * HSTR + kb + 8);
            uint32_t al3 = *(const uint32_t*)(hl + (g + 8) * HSTR + kb + 8);
#pragma unroll
            for (int nf = 0; nf < 4; nf++) {
                uint32_t wl0 = sWl[((kf * 4 + nf) * 2 + 0) * 512 + tid];
                uint32_t wl1 = sWl[((kf * 4 + nf) * 2 + 1) * 512 + tid];
                mma16816(acc[nf], ah0, ah1, ah2, ah3, wh[kf][nf][0], wh[kf][nf][1]);
                mma16816(acc[nf], al0, al1, al2, al3, wh[kf][nf][0], wh[kf][nf][1]);
                mma16816(acc[nf], ah0, ah1, ah2, ah3, wl0, wl1);
            }
        }

        // gates -> smem
#pragma unroll
        for (int nf = 0; nf < 4; nf++) {
            const int col = n0 + nf * 8 + 2 * tig;
            *(float2*)(gsm + g * GST + col)       = make_float2(acc[nf][0], acc[nf][1]);
            *(float2*)(gsm + (g + 8) * GST + col) = make_float2(acc[nf][2], acc[nf][3]);
        }
        __syncthreads();

        // elementwise: warp w = batch row w, 4 h per lane
        {
            const int b = w, j0 = lane * 4;
            const float* gb = gsm + b * GST;
            float* cb = csm + b * HID;
            float4 gi4 = *(const float4*)(gb + j0);
            float4 gf4 = *(const float4*)(gb + HID + j0);
            float4 gg4 = *(const float4*)(gb + 2 * HID + j0);
            float4 go4 = *(const float4*)(gb + 3 * HID + j0);
            float4 c4  = *(const float4*)(cb + j0);
            c4.x = sigm(gf4.x) * c4.x + sigm(gi4.x) * tanhx(gg4.x);
            c4.y = sigm(gf4.y) * c4.y + sigm(gi4.y) * tanhx(gg4.y);
            c4.z = sigm(gf4.z) * c4.z + sigm(gi4.z) * tanhx(gg4.z);
            c4.w = sigm(gf4.w) * c4.w + sigm(gi4.w) * tanhx(gg4.w);
            float hv0 = sigm(go4.x) * tanhx(c4.x);
            float hv1 = sigm(go4.y) * tanhx(c4.y);
            float hv2 = sigm(go4.z) * tanhx(c4.z);
            float hv3 = sigm(go4.w) * tanhx(c4.w);
            *(float4*)(cb + j0) = c4;
            uint32_t hi01 = packbf2(hv0, hv1), hi23 = packbf2(hv2, hv3);
            __nv_bfloat162 h01 = *(__nv_bfloat162*)&hi01;
            __nv_bfloat162 h23 = *(__nv_bfloat162*)&hi23;
            uint32_t lo01 = packbf2(hv0 - __bfloat162float(h01.x), hv1 - __bfloat162float(h01.y));
            uint32_t lo23 = packbf2(hv2 - __bfloat162float(h23.x), hv3 - __bfloat162float(h23.y));
            *(uint32_t*)(hh + b * HSTR + j0)     = hi01;
            *(uint32_t*)(hh + b * HSTR + j0 + 2) = hi23;
            *(uint32_t*)(hl + b * HSTR + j0)     = lo01;
            *(uint32_t*)(hl + b * HSTR + j0 + 2) = lo23;
            if (L0) {
                size_t rowoff = ((size_t)tg * BATCH + b0 + b) * 256 + dir * HID + j0;
                *(uint2*)(g_ah + rowoff) = make_uint2(hi01, hi23);
                *(uint2*)(g_al + rowoff) = make_uint2(lo01, lo23);
            }
        }
        __syncthreads();
    }

    // state save (+ final hidden on last L1 segment)
    for (int i = tid; i < 16 * HID; i += 512) {
        int b = i >> 7, j = i & 127;
        float h = __bfloat162float(hh[b * HSTR + j]) + __bfloat162float(hl[b * HSTR + j]);
        g_hstate[(dir * BATCH + b0 + b) * HID + j] = h;
        g_cstate[(dir * BATCH + b0 + b) * HID + j] = csm[b * HID + j];
        if (!L0 && seg == NSEG - 1)
            g_final[(size_t)(b0 + b) * 256 + dir * HID + j] = h;
    }
}

// ---------------------------------------------------------------------------
// Classifier
// ---------------------------------------------------------------------------
__global__ void k_cls(const float* __restrict__ wc, const float* __restrict__ bc,
                      float* __restrict__ out) {
    int gw   = (blockIdx.x * blockDim.x + threadIdx.x) >> 5;
    int lane = threadIdx.x & 31;
    if (gw >= BATCH) return;
    const float* f = g_final + (size_t)gw * 256;
    float v[8];
#pragma unroll
    for (int i = 0; i < 8; i++) v[i] = f[lane + 32 * i];
#pragma unroll
    for (int nc = 0; nc < NCLS; nc++) {
        float s = 0.f;
#pragma unroll
        for (int i = 0; i < 8; i++) s += v[i] * wc[nc * 256 + lane + 32 * i];
#pragma unroll
        for (int off = 16; off; off >>= 1) s += __shfl_down_sync(0xffffffffu, s, off);
        if (lane == 0) out[gw * NCLS + nc] = s + bc[nc];
    }
}

// ---------------------------------------------------------------------------
extern "C" void kernel_launch(void* const* d_in, const int* in_sizes, int n_in,
                              void* d_out, int out_size) {
    (void)in_sizes; (void)n_in; (void)out_size;
    const float* x = (const float*)d_in[0];

    (void)cudaFuncSetAttribute(k_lstm<true>,  cudaFuncAttributeMaxDynamicSharedMemorySize, SC_SMEM);
    (void)cudaFuncSetAttribute(k_lstm<false>, cudaFuncAttributeMaxDynamicSharedMemorySize, SC_SMEM);
    (void)cudaFuncSetAttribute(k_xg1,         cudaFuncAttributeMaxDynamicSharedMemorySize, XSMEM);
    (void)cudaFuncSetAttribute(k_xg0,         cudaFuncAttributeMaxDynamicSharedMemorySize, 20480);

    WPtrs W;
    for (int i = 0; i < 16; i++) W.p[i] = (const float*)d_in[1 + i];

    k_transpose<<<(TLEN * BATCH * 16 + 255) / 256, 256>>>(x);
    k_pack_bias<<<8, 256>>>(W);
    k_pack_wfrag<<<(4 * 32768 + 255) / 256, 256>>>(W);
    k_pack_wb1<<<(2 * G4 * 256 + 255) / 256, 256>>>((const float*)d_in[9], (const float*)d_in[13]);

    for (int seg = 0; seg < NSEG; seg++) {
        k_xg0<<<dim3((SEGT * BATCH) / 32, 2), 256, 20480>>>(W, seg);
        k_lstm<true><<<dim3(BATCH / BT, 2), 512, SC_SMEM>>>(seg);
    }
    for (int seg = 0; seg < NSEG; seg++) {
        k_xg1<<<dim3(8, (SEGT * BATCH) / 128), 256, XSMEM>>>(seg);
        k_lstm<false><<<dim3(BATCH / BT, 2), 512, SC_SMEM>>>(seg);
    }

    k_cls<<<BATCH / 8, 256>>>((const float*)d_in[17], (const float*)d_in[18], (float*)d_out);
}

// round 17
// speedup vs baseline: 2.0257x; 1.0763x over previous
#include <cuda_runtime.h>
#include <cuda_bf16.h>
#include <cstdint>

#define TLEN  512
#define BATCH 1024
#define HID   128
#define G4    512
#define NCLS  6
#define BT    16
#define SEGT  128
#define NSEG  (TLEN / SEGT)
#define HSTR  136    // h smem row stride (bf16)

// gate permutation: packed column n' holds source gate G = (n'&3)*128 + (n'>>2)
__host__ __device__ __forceinline__ int gperm(int n) { return (n & 3) * 128 + (n >> 2); }

// ---------------------------------------------------------------------------
// Scratch
// ---------------------------------------------------------------------------
__device__ __align__(16) float g_xT[(size_t)TLEN * BATCH * 16];
__device__ __align__(16) __nv_bfloat16 g_ah[(size_t)TLEN * BATCH * 256];
__device__ __align__(16) __nv_bfloat16 g_al[(size_t)TLEN * BATCH * 256];
__device__ __align__(16) float g_xg1f[(size_t)SEGT * BATCH * G4];
__device__ __align__(16) float g_xg1r[(size_t)SEGT * BATCH * G4];
__device__ __align__(16) float g_hstate[2 * BATCH * HID];
__device__ __align__(16) float g_cstate[2 * BATCH * HID];
__device__ __align__(16) float g_final[(size_t)BATCH * 256];
__device__ __align__(16) uint32_t g_wfh[4 * 32768];
__device__ __align__(16) uint32_t g_wfl[4 * 32768];
__device__ __align__(16) __nv_bfloat16 g_wb1h[2 * 512 * 256];
__device__ __align__(16) __nv_bfloat16 g_wb1l[2 * 512 * 256];
__device__ float g_bias[4 * G4];

extern __shared__ char smem_raw[];

// ---------------------------------------------------------------------------
// Helpers
// ---------------------------------------------------------------------------
__device__ __forceinline__ float sigm(float x) {
    return __fdividef(1.f, 1.f + __expf(-x));
}
__device__ __forceinline__ float tanhx(float x) {
    return __fdividef(2.f, 1.f + __expf(-2.f * x)) - 1.f;
}
__device__ __forceinline__ uint32_t smem_u32(const void* p) {
    uint32_t a;
    asm("{ .reg .u64 t; cvta.to.shared.u64 t, %1; cvt.u32.u64 %0, t; }" : "=r"(a) : "l"(p));
    return a;
}
__device__ __forceinline__ void cp16(uint32_t saddr, const void* gptr) {
    asm volatile("cp.async.cg.shared.global [%0], [%1], 16;"
                 :: "r"(saddr), "l"(gptr) : "memory");
}
__device__ __forceinline__ uint32_t packbf2(float a, float b) {
    __nv_bfloat162 p = {__float2bfloat16(a), __float2bfloat16(b)};
    return *(uint32_t*)&p;
}
__device__ __forceinline__ void mma16816(float* c,
                                         uint32_t a0, uint32_t a1, uint32_t a2, uint32_t a3,
                                         uint32_t b0, uint32_t b1) {
    asm volatile(
        "mma.sync.aligned.m16n8k16.row.col.f32.bf16.bf16.f32 "
        "{%0,%1,%2,%3}, {%4,%5,%6,%7}, {%8,%9}, {%0,%1,%2,%3};"
        : "+f"(c[0]), "+f"(c[1]), "+f"(c[2]), "+f"(c[3])
        : "r"(a0), "r"(a1), "r"(a2), "r"(a3), "r"(b0), "r"(b1));
}

struct WPtrs { const float* p[16]; };

// ---------------------------------------------------------------------------
// Prep: transpose x [B,9,T] -> g_xT [T,B,16]
// ---------------------------------------------------------------------------
__global__ void k_transpose(const float* __restrict__ x) {
    size_t o = (size_t)blockIdx.x * blockDim.x + threadIdx.x;
    if (o >= (size_t)TLEN * BATCH * 16) return;
    int c = (int)(o & 15);
    size_t tb = o >> 4;
    int b = (int)(tb % BATCH);
    int t = (int)(tb / BATCH);
    g_xT[o] = (c < 9) ? x[((size_t)b * 9 + c) * TLEN + t] : 0.f;
}

// ---------------------------------------------------------------------------
// Bias sums in PERMUTED order
// ---------------------------------------------------------------------------
__global__ void k_pack_bias(WPtrs W) {
    int o = blockIdx.x * 256 + threadIdx.x;
    if (o >= 4 * G4) return;
    int which = o >> 9, n = o & 511;
    int G = gperm(n);
    g_bias[o] = W.p[which * 4 + 2][G] + W.p[which * 4 + 3][G];
}

// ---------------------------------------------------------------------------
// W_hh -> m16n8k16 B-fragments (permuted columns), bf16 hi/lo
// ---------------------------------------------------------------------------
__global__ void k_pack_wfrag(WPtrs W) {
    int o = blockIdx.x * 256 + threadIdx.x;
    if (o >= 4 * 32768) return;
    int which = o >> 15;
    int rem = o & 32767;
    int pos = rem & 511;
    int rr  = rem >> 9;
    int r = rr & 1, nf = (rr >> 1) & 3, kf = rr >> 3;
    int lane = pos & 31;
    int n = (pos >> 5) * 32 + nf * 8 + (lane >> 2);
    int k = kf * 16 + r * 8 + 2 * (lane & 3);
    const float* whh = W.p[which * 4 + 1];
    int G = gperm(n);
    float w0 = whh[G * HID + k], w1 = whh[G * HID + k + 1];
    __nv_bfloat16 h0 = __float2bfloat16(w0), h1 = __float2bfloat16(w1);
    g_wfh[o] = packbf2(__bfloat162float(h0), __bfloat162float(h1));
    g_wfl[o] = packbf2(w0 - __bfloat162float(h0), w1 - __bfloat162float(h1));
}

// ---------------------------------------------------------------------------
// W_ih_l1 -> bf16 hi/lo rows in PERMUTED order
// ---------------------------------------------------------------------------
__global__ void k_pack_wb1(const float* __restrict__ wf, const float* __restrict__ wr) {
    int o = blockIdx.x * blockDim.x + threadIdx.x;
    if (o >= 2 * G4 * 256) return;
    int dir = o / (G4 * 256);
    int rem = o % (G4 * 256);
    int n = rem / 256, k = rem % 256;
    const float* w = dir ? wr : wf;
    float v = w[gperm(n) * 256 + k];
    __nv_bfloat16 h = __float2bfloat16(v);
    g_wb1h[o] = h;
    g_wb1l[o] = __float2bfloat16(v - __bfloat162float(h));
}

// ---------------------------------------------------------------------------
// xg0 chunk: L0 input projection (K=9, fp32), PERMUTED columns + bias
// ---------------------------------------------------------------------------
__global__ void __launch_bounds__(256, 4) k_xg0(WPtrs W, int seg) {
    float* sW = (float*)smem_raw;          // [512*9] permuted rows
    float* sb = sW + 512 * 9;
    const int tid = threadIdx.x, wid = tid >> 5, lane = tid & 31;
    const int dir = blockIdx.y;
    const float* wih = W.p[dir * 4 + 0];
    for (int i = tid; i < 512 * 9; i += 256) {
        int n = i / 9, k = i % 9;
        sW[i] = wih[gperm(n) * 9 + k];
    }
    for (int i = tid; i < 512; i += 256) sb[i] = g_bias[dir * 512 + i];
    __syncthreads();
    const int t0 = dir ? (TLEN - (seg + 1) * SEGT) : (seg * SEGT);
    float* out = dir ? g_xg1r : g_xg1f;
    const float* xbase = g_xT + (size_t)t0 * BATCH * 16;
    const size_t rbase = (size_t)blockIdx.x * 32 + wid * 4;
    for (int rr = 0; rr < 4; rr++) {
        size_t row = rbase + rr;
        const float* xr = xbase + row * 16;
        float xv[9];
#pragma unroll
        for (int k = 0; k < 9; k++) xv[k] = xr[k];
#pragma unroll
        for (int cblk = 0; cblk < 4; cblk++) {
            int gbase = cblk * 128 + lane * 4;
            float4 o4;
            float* po = &o4.x;
#pragma unroll
            for (int u = 0; u < 4; u++) {
                int G = gbase + u;
                float s = sb[G];
#pragma unroll
                for (int k = 0; k < 9; k++) s += xv[k] * sW[G * 9 + k];
                po[u] = s;
            }
            *(float4*)(out + row * 512 + gbase) = o4;
        }
    }
}

// ---------------------------------------------------------------------------
// xg1 chunk GEMM (body unchanged; inputs already permuted)
// ---------------------------------------------------------------------------
#define XSTR   40
#define XMAT   (128 * XSTR)
#define XSTAGE (4 * XMAT)
#define XSMEM  (2 * XSTAGE * 2)

__global__ void __launch_bounds__(256, 2) k_xg1(int seg) {
    __nv_bfloat16* sm = (__nv_bfloat16*)smem_raw;
    const uint32_t sbase = smem_u32(sm);

    const int tid  = threadIdx.x;
    const int wid  = tid >> 5, lane = tid & 31;
    const int g    = lane >> 2, tig = lane & 3;
    const int wm   = (wid & 1) * 64;
    const int wn   = (wid >> 1) * 32;
    const int dir  = blockIdx.x >> 2;
    const int n0   = (blockIdx.x & 3) * 128;
    const int t0   = dir ? (TLEN - (seg + 1) * SEGT) : (seg * SEGT);
    const size_t mg0 = (size_t)t0 * BATCH + (size_t)blockIdx.y * 128;
    const size_t ml0 = (size_t)blockIdx.y * 128;

    const __nv_bfloat16* gBh = g_wb1h + ((size_t)dir * 512 + n0) * 256;
    const __nv_bfloat16* gBl = g_wb1l + ((size_t)dir * 512 + n0) * 256;

    auto load_stage = [&](int kc, int stage) {
        const uint32_t sb = sbase + (uint32_t)stage * XSTAGE * 2;
#pragma unroll
        for (int j = 0; j < 8; j++) {
            int i = tid + 256 * j;
            int mat = i >> 9;
            int r   = (i >> 2) & 127;
            int c   = i & 3;
            const __nv_bfloat16* gp;
            if (mat == 0)      gp = g_ah + (mg0 + r) * 256 + kc * 32 + c * 8;
            else if (mat == 1) gp = g_al + (mg0 + r) * 256 + kc * 32 + c * 8;
            else if (mat == 2) gp = gBh + (size_t)r * 256 + kc * 32 + c * 8;
            else               gp = gBl + (size_t)r * 256 + kc * 32 + c * 8;
            uint32_t sa = sb + (uint32_t)(mat * XMAT + r * XSTR + c * 8) * 2;
            cp16(sa, gp);
        }
        asm volatile("cp.async.commit_group;" ::: "memory");
    };

    float acc[4][4][4];
#pragma unroll
    for (int mf = 0; mf < 4; mf++)
#pragma unroll
        for (int nf = 0; nf < 4; nf++)
#pragma unroll
            for (int q = 0; q < 4; q++) acc[mf][nf][q] = 0.f;

    load_stage(0, 0);

    for (int kc = 0; kc < 8; kc++) {
        if (kc + 1 < 8) {
            load_stage(kc + 1, (kc + 1) & 1);
            asm volatile("cp.async.wait_group 1;" ::: "memory");
        } else {
            asm volatile("cp.async.wait_group 0;" ::: "memory");
        }
        __syncthreads();

        const __nv_bfloat16* sAh = sm + (kc & 1) * XSTAGE;
        const __nv_bfloat16* sAl = sAh + XMAT;
        const __nv_bfloat16* sBh = sAh + 2 * XMAT;
        const __nv_bfloat16* sBl = sAh + 3 * XMAT;

#pragma unroll
        for (int s = 0; s < 2; s++) {
            const int kb = s * 16 + 2 * tig;
            uint32_t bh[4][2], bl[4][2];
#pragma unroll
            for (int nf = 0; nf < 4; nf++) {
                const int n = wn + nf * 8 + g;
                bh[nf][0] = *(const uint32_t*)(sBh + n * XSTR + kb);
                bh[nf][1] = *(const uint32_t*)(sBh + n * XSTR + kb + 8);
                bl[nf][0] = *(const uint32_t*)(sBl + n * XSTR + kb);
                bl[nf][1] = *(const uint32_t*)(sBl + n * XSTR + kb + 8);
            }
#pragma unroll
            for (int mf = 0; mf < 4; mf++) {
                const int mr = wm + mf * 16 + g;
                uint32_t ah0 = *(const uint32_t*)(sAh + mr * XSTR + kb);
                uint32_t ah1 = *(const uint32_t*)(sAh + (mr + 8) * XSTR + kb);
                uint32_t ah2 = *(const uint32_t*)(sAh + mr * XSTR + kb + 8);
                uint32_t ah3 = *(const uint32_t*)(sAh + (mr + 8) * XSTR + kb + 8);
                uint32_t al0 = *(const uint32_t*)(sAl + mr * XSTR + kb);
                uint32_t al1 = *(const uint32_t*)(sAl + (mr + 8) * XSTR + kb);
                uint32_t al2 = *(const uint32_t*)(sAl + mr * XSTR + kb + 8);
                uint32_t al3 = *(const uint32_t*)(sAl + (mr + 8) * XSTR + kb + 8);
#pragma unroll
                for (int nf = 0; nf < 4; nf++) {
                    mma16816(acc[mf][nf], ah0, ah1, ah2, ah3, bh[nf][0], bh[nf][1]);
                    mma16816(acc[mf][nf], ah0, ah1, ah2, ah3, bl[nf][0], bl[nf][1]);
                    mma16816(acc[mf][nf], al0, al1, al2, al3, bh[nf][0], bh[nf][1]);
                }
            }
        }
        __syncthreads();
    }

    float* out = dir ? g_xg1r : g_xg1f;
    const float* bias = g_bias + (2 + dir) * G4 + n0;
#pragma unroll
    for (int mf = 0; mf < 4; mf++) {
#pragma unroll
        for (int nf = 0; nf < 4; nf++) {
            const int col = wn + nf * 8 + 2 * tig;
            const size_t row = ml0 + wm + mf * 16 + g;
            float2 bv = *(const float2*)(bias + col);
            float2 v0 = make_float2(acc[mf][nf][0] + bv.x, acc[mf][nf][1] + bv.y);
            float2 v1 = make_float2(acc[mf][nf][2] + bv.x, acc[mf][nf][3] + bv.y);
            *(float2*)(out + row * G4 + n0 + col)       = v0;
            *(float2*)(out + (row + 8) * G4 + n0 + col) = v1;
        }
    }
}

// ---------------------------------------------------------------------------
// BiLSTM scan: mma.sync recurrence, interleaved gates, in-warp elementwise,
// DOUBLE-BUFFERED h (read buf t&1, write buf (t+1)&1) -> no intra-step race,
// exactly 1 __syncthreads per step (both layers).  c in registers.
// smem: sWl 128K | hbuf[2] x (hh,hl) 16x136 bf16
// ---------------------------------------------------------------------------
#define HBUF  (32 * HSTR)                      // one buffer: hh + hl (bf16 elems)
#define SC_SMEM (131072 + 2 * HBUF * 2)        // 148480

template <bool L0>
__global__ void __launch_bounds__(512, 1) k_lstm(int seg) {
    uint32_t* sWl = (uint32_t*)smem_raw;
    __nv_bfloat16* hbuf = (__nv_bfloat16*)(smem_raw + 131072);

    const int tid = threadIdx.x;
    const int w = tid >> 5, lane = tid & 31;
    const int g = lane >> 2, tig = lane & 3;
    const int dir = blockIdx.y;
    const int b0 = blockIdx.x * BT;
    const int which = (L0 ? 0 : 2) + dir;
    const uint32_t* wfh = g_wfh + (size_t)which * 32768;
    const uint32_t* wfl = g_wfl + (size_t)which * 32768;
    const float* __restrict__ xgb = dir ? g_xg1r : g_xg1f;
    const int tbase = dir ? (TLEN - (seg + 1) * SEGT) : (seg * SEGT);
    const int n0 = w * 32;

    // lane's elementwise cells: row mrow, hidden j = jlo + 2*nf
    const int mrow = (tig & 1) ? (g + 8) : g;
    const int jlo  = 8 * w + (tig >> 1);

    // Wh -> registers
    uint32_t wh[8][4][2];
#pragma unroll
    for (int kf = 0; kf < 8; kf++)
#pragma unroll
        for (int nf = 0; nf < 4; nf++)
#pragma unroll
            for (int r = 0; r < 2; r++)
                wh[kf][nf][r] = wfh[((kf * 4 + nf) * 2 + r) * 512 + tid];
    // Wl -> smem
    for (int i = tid; i < 8192; i += 512)
        ((uint4*)sWl)[i] = ((const uint4*)wfl)[i];

    // state init into buffer 0 (t=0 reads buf 0)
    float c[4];
    if (seg == 0) {
        for (int i = tid; i < HBUF; i += 512) hbuf[i] = __float2bfloat16(0.f);
#pragma unroll
        for (int nf = 0; nf < 4; nf++) c[nf] = 0.f;
    } else {
        for (int i = tid; i < 16 * HID; i += 512) {
            int b = i >> 7, j = i & 127;
            float h = g_hstate[(dir * BATCH + b0 + b) * HID + j];
            __nv_bfloat16 h0 = __float2bfloat16(h);
            hbuf[b * HSTR + j]            = h0;
            hbuf[16 * HSTR + b * HSTR + j] = __float2bfloat16(h - __bfloat162float(h0));
        }
#pragma unroll
        for (int nf = 0; nf < 4; nf++)
            c[nf] = g_cstate[(dir * BATCH + b0 + mrow) * HID + jlo + 2 * nf];
    }
    __syncthreads();

    // xg prefetch regs
    float xn[4][4];
    auto ldxg = [&](int tl) {
        const float* x0 = xgb + ((size_t)tl * BATCH + b0 + g) * G4 + n0;
        const float* x1 = x0 + 8 * G4;
#pragma unroll
        for (int nf = 0; nf < 4; nf++) {
            float2 p0 = *(const float2*)(x0 + nf * 8 + 2 * tig);
            float2 p1 = *(const float2*)(x1 + nf * 8 + 2 * tig);
            xn[nf][0] = p0.x; xn[nf][1] = p0.y; xn[nf][2] = p1.x; xn[nf][3] = p1.y;
        }
    };
    ldxg(dir ? SEGT - 1 : 0);

    for (int t = 0; t < SEGT; ++t) {
        const int tl = dir ? (SEGT - 1 - t) : t;
        const int tg = tbase + tl;
        const int rb = t & 1;
        __nv_bfloat16* hh = hbuf + rb * HBUF;
        __nv_bfloat16* hl = hh + 16 * HSTR;
        __nv_bfloat16* nhh = hbuf + (rb ^ 1) * HBUF;
        __nv_bfloat16* nhl = nhh + 16 * HSTR;

        float acc[4][4];
#pragma unroll
        for (int nf = 0; nf < 4; nf++)
#pragma unroll
            for (int q = 0; q < 4; q++) acc[nf][q] = xn[nf][q];

        // gates += h @ Whh^T (3-split)
#pragma unroll
        for (int kf = 0; kf < 8; kf++) {
            const int kb = kf * 16 + 2 * tig;
            uint32_t ah0 = *(const uint32_t*)(hh + g * HSTR + kb);
            uint32_t ah1 = *(const uint32_t*)(hh + (g + 8) * HSTR + kb);
            uint32_t ah2 = *(const uint32_t*)(hh + g * HSTR + kb + 8);
            uint32_t ah3 = *(const uint32_t*)(hh + (g + 8) * HSTR + kb + 8);
            uint32_t al0 = *(const uint32_t*)(hl + g * HSTR + kb);
            uint32_t al1 = *(const uint32_t*)(hl + (g + 8) * HSTR + kb);
            uint32_t al2 = *(const uint32_t*)(hl + g * HSTR + kb + 8);
            uint32_t al3 = *(const uint32_t*)(hl + (g + 8) * HSTR + kb + 8);
#pragma unroll
            for (int nf = 0; nf < 4; nf++) {
                uint32_t wl0 = sWl[((kf * 4 + nf) * 2 + 0) * 512 + tid];
                uint32_t wl1 = sWl[((kf * 4 + nf) * 2 + 1) * 512 + tid];
                mma16816(acc[nf], ah0, ah1, ah2, ah3, wh[kf][nf][0], wh[kf][nf][1]);
                mma16816(acc[nf], al0, al1, al2, al3, wh[kf][nf][0], wh[kf][nf][1]);
                mma16816(acc[nf], ah0, ah1, ah2, ah3, wl0, wl1);
            }
        }

        // in-warp gate exchange + elementwise (writes go to the OTHER buffer)
#pragma unroll
        for (int nf = 0; nf < 4; nf++) {
            float e0 = __shfl_xor_sync(0xffffffffu, acc[nf][0], 1);
            float e1 = __shfl_xor_sync(0xffffffffu, acc[nf][1], 1);
            float e2 = __shfl_xor_sync(0xffffffffu, acc[nf][2], 1);
            float e3 = __shfl_xor_sync(0xffffffffu, acc[nf][3], 1);
            float vi, vf, vg, vo;
            if (!(tig & 1)) { vi = acc[nf][0]; vf = acc[nf][1]; vg = e0; vo = e1; }
            else            { vi = e2; vf = e3; vg = acc[nf][2]; vo = acc[nf][3]; }
            float cc = sigm(vf) * c[nf] + sigm(vi) * tanhx(vg);
            c[nf] = cc;
            float hv = sigm(vo) * tanhx(cc);
            __nv_bfloat16 hb = __float2bfloat16(hv);
            nhh[mrow * HSTR + jlo + 2 * nf] = hb;
            nhl[mrow * HSTR + jlo + 2 * nf] = __float2bfloat16(hv - __bfloat162float(hb));
        }

        if (t + 1 < SEGT) ldxg(dir ? (SEGT - 2 - t) : (t + 1));
        __syncthreads();   // new h visible; old buffer free next step

        if (L0) {
            // copy freshly written buffer (read-only next step -> safe, no 2nd sync)
            const int row = tid >> 5, c4 = (tid & 31) * 4;
            size_t off = ((size_t)tg * BATCH + b0 + row) * 256 + dir * HID + c4;
            *(uint2*)(g_ah + off) = *(uint2*)(nhh + row * HSTR + c4);
            *(uint2*)(g_al + off) = *(uint2*)(nhl + row * HSTR + c4);
        }
    }

    // final h in buffer (SEGT & 1) = 0
    for (int i = tid; i < 16 * HID; i += 512) {
        int b = i >> 7, j = i & 127;
        float h = __bfloat162float(hbuf[b * HSTR + j]) +
                  __bfloat162float(hbuf[16 * HSTR + b * HSTR + j]);
        g_hstate[(dir * BATCH + b0 + b) * HID + j] = h;
        if (!L0 && seg == NSEG - 1)
            g_final[(size_t)(b0 + b) * 256 + dir * HID + j] = h;
    }
#pragma unroll
    for (int nf = 0; nf < 4; nf++)
        g_cstate[(dir * BATCH + b0 + mrow) * HID + jlo + 2 * nf] = c[nf];
}

// ---------------------------------------------------------------------------
// Classifier
// ---------------------------------------------------------------------------
__global__ void k_cls(const float* __restrict__ wc, const float* __restrict__ bc,
                      float* __restrict__ out) {
    int gw   = (blockIdx.x * blockDim.x + threadIdx.x) >> 5;
    int lane = threadIdx.x & 31;
    if (gw >= BATCH) return;
    const float* f = g_final + (size_t)gw * 256;
    float v[8];
#pragma unroll
    for (int i = 0; i < 8; i++) v[i] = f[lane + 32 * i];
#pragma unroll
    for (int nc = 0; nc < NCLS; nc++) {
        float s = 0.f;
#pragma unroll
        for (int i = 0; i < 8; i++) s += v[i] * wc[nc * 256 + lane + 32 * i];
#pragma unroll
        for (int off = 16; off; off >>= 1) s += __shfl_down_sync(0xffffffffu, s, off);
        if (lane == 0) out[gw * NCLS + nc] = s + bc[nc];
    }
}

// ---------------------------------------------------------------------------
extern "C" void kernel_launch(void* const* d_in, const int* in_sizes, int n_in,
                              void* d_out, int out_size) {
    (void)in_sizes; (void)n_in; (void)out_size;
    const float* x = (const float*)d_in[0];

    (void)cudaFuncSetAttribute(k_lstm<true>,  cudaFuncAttributeMaxDynamicSharedMemorySize, SC_SMEM);
    (void)cudaFuncSetAttribute(k_lstm<false>, cudaFuncAttributeMaxDynamicSharedMemorySize, SC_SMEM);
    (void)cudaFuncSetAttribute(k_xg1,         cudaFuncAttributeMaxDynamicSharedMemorySize, XSMEM);
    (void)cudaFuncSetAttribute(k_xg0,         cudaFuncAttributeMaxDynamicSharedMemorySize, 20480);

    WPtrs W;
    for (int i = 0; i < 16; i++) W.p[i] = (const float*)d_in[1 + i];

    k_transpose<<<(TLEN * BATCH * 16 + 255) / 256, 256>>>(x);
    k_pack_bias<<<8, 256>>>(W);
    k_pack_wfrag<<<(4 * 32768 + 255) / 256, 256>>>(W);
    k_pack_wb1<<<(2 * G4 * 256 + 255) / 256, 256>>>((const float*)d_in[9], (const float*)d_in[13]);

    for (int seg = 0; seg < NSEG; seg++) {
        k_xg0<<<dim3((SEGT * BATCH) / 32, 2), 256, 20480>>>(W, seg);
        k_lstm<true><<<dim3(BATCH / BT, 2), 512, SC_SMEM>>>(seg);
    }
    for (int seg = 0; seg < NSEG; seg++) {
        k_xg1<<<dim3(8, (SEGT * BATCH) / 128), 256, XSMEM>>>(seg);
        k_lstm<false><<<dim3(BATCH / BT, 2), 512, SC_SMEM>>>(seg);
    }

    k_cls<<<BATCH / 8, 256>>>((const float*)d_in[17], (const float*)d_in[18], (float*)d_out);
}